// round 10
// baseline (speedup 1.0000x reference)
#include <cuda_runtime.h>
#include <stdint.h>
#include <math.h>

// ---------------- dims ----------------
#define B_ 64
#define NMAX_ 256
#define TOBS_ 16
#define DIN_ 2
#define E_ 128
#define DMODEL_ 512
#define BN_ROWS (B_ * NMAX_)            // 16384
#define MROWS (BN_ROWS * TOBS_)         // 262144
#define HROW (TOBS_ * E_)               // 2048
#define QKV_N 1536

// ---------------- scratch (device globals; no runtime alloc) ----------------
__device__ float g_h[(size_t)BN_ROWS * HROW];    // [bn][t][e]
__device__ float g_z[(size_t)BN_ROWS * HROW];
__device__ float g_feat[(size_t)BN_ROWS * DMODEL_];
__device__ float g_qkv[(size_t)BN_ROWS * QKV_N]; // [bn][ q(512) | k(512) | v(512) ]
__device__ float g_att[(size_t)BN_ROWS * DMODEL_];
__device__ float g_o[(size_t)BN_ROWS * DMODEL_];
__device__ float g_p1[(size_t)BN_ROWS * 1024];
__device__ float g_p2[(size_t)BN_ROWS * 1024];
__device__ float g_wc[6 * 384 * 128];            // [blk*2+conv][tap*128+i][o]
__device__ float g_wqkv[DMODEL_ * QKV_N];        // [k][ wq | wk | wv ]
__device__ float g_bqkv[QKV_N];
__device__ int   g_mask[BN_ROWS];

// ---------------- cp.async helpers ----------------
__device__ __forceinline__ void cp_async16(uint32_t smem_addr, const void* gptr) {
    asm volatile("cp.async.cg.shared.global [%0], [%1], 16;\n"
                 :: "r"(smem_addr), "l"(gptr));
}
__device__ __forceinline__ void cp_async_commit() {
    asm volatile("cp.async.commit_group;\n" ::);
}
__device__ __forceinline__ void cp_async_wait_all() {
    asm volatile("cp.async.wait_group 0;\n" ::: "memory");
}

// ---------------- active-agent mask ----------------
__global__ void mask_kernel(const float* __restrict__ x, int* __restrict__ mask) {
    int b = blockIdx.x;
    int n = threadIdx.x;
    const float* p = x + (size_t)(b * NMAX_ + n) * (TOBS_ * DIN_);
    float s = 0.f;
#pragma unroll
    for (int j = 0; j < TOBS_ * DIN_; j++) s += p[j];
    __shared__ int cnt;
    if (n == 0) cnt = 0;
    __syncthreads();
    if (s > 0.0f) atomicAdd(&cnt, 1);
    __syncthreads();
    mask[b * NMAX_ + n] = (n < cnt) ? 1 : 0;
}

// ---------------- embedding: h[bn,t,e] = x0*w[0,e]+x1*w[1,e]+b[e] ----------------
__global__ void emb_kernel(const float* __restrict__ x, const float* __restrict__ w,
                           const float* __restrict__ bias, float* __restrict__ h) {
    size_t idx = (size_t)blockIdx.x * blockDim.x + threadIdx.x;
    if (idx >= (size_t)MROWS * E_) return;
    int e = (int)(idx & (E_ - 1));
    size_t row = idx >> 7;                 // bn*16+t
    float x0 = x[row * 2 + 0];
    float x1 = x[row * 2 + 1];
    h[idx] = fmaf(x0, w[e], fmaf(x1, w[E_ + e], bias[e]));
}

// ---------------- conv weight transform: w[o][i][tap] -> wc[kk=tap*128+i][o] ----------------
__global__ void wprep_kernel(const float* __restrict__ w1, const float* __restrict__ w2,
                             float* __restrict__ out) {
    int t = blockIdx.x * blockDim.x + threadIdx.x;
    if (t >= 6 * 49152) return;
    int bc = t / 49152;       // blk*2 + conv
    int r = t % 49152;        // kk*128 + o
    int kk = r >> 7;
    int o = r & 127;
    int tap = kk >> 7;
    int i = kk & 127;
    int blk = bc >> 1, conv = bc & 1;
    const float* src = conv ? w2 : w1;
    out[t] = src[(((size_t)(blk * 128 + o) * 128 + i) * 3) + tap];
}

// ---------------- QKV weight/bias packing: [512][1536] = wq|wk|wv ----------------
__global__ void qkvprep_kernel(const float* __restrict__ wq, const float* __restrict__ wk,
                               const float* __restrict__ wv,
                               const float* __restrict__ bq, const float* __restrict__ bk,
                               const float* __restrict__ bv,
                               float* __restrict__ wout, float* __restrict__ bout) {
    int t = blockIdx.x * blockDim.x + threadIdx.x;
    if (t < DMODEL_ * QKV_N) {
        int k = t / QKV_N;
        int n = t % QKV_N;
        int sel = n >> 9;              // 0:q 1:k 2:v
        int nn = n & 511;
        const float* src = (sel == 0) ? wq : (sel == 1) ? wk : wv;
        wout[t] = src[(size_t)k * DMODEL_ + nn];
    }
    if (t < QKV_N) {
        int sel = t >> 9;
        int nn = t & 511;
        bout[t] = (sel == 0) ? bq[nn] : (sel == 1) ? bk[nn] : bv[nn];
    }
}

// ---------------- zero inactive agent rows of h ----------------
__global__ void maskapply_kernel(float* __restrict__ h, const int* __restrict__ mask) {
    int bn = blockIdx.x;
    if (mask[bn]) return;
    float4 z = make_float4(0.f, 0.f, 0.f, 0.f);
    float4* p = (float4*)(h + (size_t)bn * HROW);
    p[threadIdx.x] = z;
    p[threadIdx.x + 256] = z;
}

// ---------------- generic tiled GEMM, double-buffered, split fragments ----------------
// BM=128, BN=128, BK=16; 8x8 acc/thread (two 4-wide halves per dim); 256 threads.
// A tile: register-staged (transposed store). B tile: cp.async (FULL path).
// Fragment halves at tm*4 / 64+tm*4 (rows) and tn*4 / 64+tn*4 (cols):
// conflict-free LDS.128 within quarter-warps.
// C[M,N] = act( A[M,K] @ B[K,N] + bias )  (+residual, +outer relu)
// CONV=1: A is implicit-gemm gather from [bn][t][128] with dilation `dil`, K=384.
//         Block covers 8 agents; exits early if all 8 are inactive (their TCN
//         output is zeroed by maskapply anyway — bitwise-identical result).
// FULL=1: N % 128 == 0 (no column bound checks anywhere).
template <int CONV, int FULL>
__global__ __launch_bounds__(256)
void gemm_kernel(const float* __restrict__ A, const float* __restrict__ Bm,
                 const float* __restrict__ bias, const float* __restrict__ res,
                 float* __restrict__ C,
                 int N, int Kdim, int lda, int ldc,
                 int relu1, int hasres, int dil,
                 const int* __restrict__ mask) {
    int tid = threadIdx.x;
    int m0 = blockIdx.x * 128;
    int n0 = blockIdx.y * 128;

    if (CONV) {
        // early-exit: 8 consecutive agents for this block; skip if all inactive
        int bn0 = m0 >> 4;
        int any = 0;
#pragma unroll
        for (int i = 0; i < 8; i++) any |= mask[bn0 + i];
        if (!any) return;
    }

    __shared__ float As[2][16][128];
    __shared__ float Bs[2][16][128];

    int tm = tid >> 4;        // 0..15
    int tn = tid & 15;        // 0..15

    // per-thread load coordinates (fixed across tiles)
    int ar0 = (tid) >> 2,        ac0 = ((tid) & 3) * 4;        // A rep0: row, k-off
    int ar1 = (256 + tid) >> 2,  ac1 = ((256 + tid) & 3) * 4;  // A rep1
    int br0 = (tid) >> 5,        bc0 = ((tid) & 31) * 4;       // B rep0: k-row, n-off
    int br1 = (256 + tid) >> 5,  bc1 = ((256 + tid) & 31) * 4; // B rep1

    // smem byte addresses for the two B cp.async destinations
    uint32_t bs0 = (uint32_t)__cvta_generic_to_shared(&Bs[0][br0][bc0]);
    uint32_t bs1 = (uint32_t)__cvta_generic_to_shared(&Bs[0][br1][bc1]);
    const uint32_t BUFB = 16 * 128 * 4;   // bytes per B buffer

    float acc[8][8];
#pragma unroll
    for (int i = 0; i < 8; i++)
#pragma unroll
        for (int j = 0; j < 8; j++) acc[i][j] = 0.f;

    int ntiles = Kdim >> 4;

    // ---- tile fetch helpers ----
    auto fetchA = [&](int k0, int r, int c4) -> float4 {
        if (CONV) {
            int m = m0 + r;
            int bn = m >> 4, t = m & 15;
            int kk = k0 + c4;
            int tap = kk >> 7;
            int e = kk & 127;
            int tsrc = t - (2 - tap) * dil;
            if (tsrc >= 0)
                return *(const float4*)(A + (size_t)bn * HROW + tsrc * E_ + e);
            return make_float4(0.f, 0.f, 0.f, 0.f);
        }
        return *(const float4*)(A + (size_t)(m0 + r) * lda + k0 + c4);
    };
    auto storeA = [&](int buf, float4 a0, float4 a1) {
        As[buf][ac0 + 0][ar0] = a0.x;
        As[buf][ac0 + 1][ar0] = a0.y;
        As[buf][ac0 + 2][ar0] = a0.z;
        As[buf][ac0 + 3][ar0] = a0.w;
        As[buf][ac1 + 0][ar1] = a1.x;
        As[buf][ac1 + 1][ar1] = a1.y;
        As[buf][ac1 + 2][ar1] = a1.z;
        As[buf][ac1 + 3][ar1] = a1.w;
    };
    // FULL: async B copy (16B each, contiguous, unconditionally in-bounds)
    auto cpB = [&](int buf, int k0) {
        cp_async16(bs0 + buf * BUFB, Bm + (size_t)(k0 + br0) * N + (n0 + bc0));
        cp_async16(bs1 + buf * BUFB, Bm + (size_t)(k0 + br1) * N + (n0 + bc1));
        cp_async_commit();
    };
    // non-FULL fallback: guarded scalar loads
    auto fetchB = [&](int k0, int r, int c) -> float4 {
        int n = n0 + c;
        const float* bp = Bm + (size_t)(k0 + r) * N + n;
        if (n + 3 < N) return *(const float4*)bp;
        float4 v;
        v.x = (n + 0 < N) ? bp[0] : 0.f;
        v.y = (n + 1 < N) ? bp[1] : 0.f;
        v.z = (n + 2 < N) ? bp[2] : 0.f;
        v.w = (n + 3 < N) ? bp[3] : 0.f;
        return v;
    };
    auto storeB = [&](int buf, float4 b0, float4 b1) {
        *(float4*)&Bs[buf][br0][bc0] = b0;
        *(float4*)&Bs[buf][br1][bc1] = b1;
    };

    // ---- prologue: tile 0 -> buf 0 ----
    {
        float4 a0 = fetchA(0, ar0, ac0);
        float4 a1 = fetchA(0, ar1, ac1);
        storeA(0, a0, a1);
        if (FULL) {
            cpB(0, 0);
            cp_async_wait_all();
        } else {
            storeB(0, fetchB(0, br0, bc0), fetchB(0, br1, bc1));
        }
    }
    __syncthreads();

    for (int it = 0; it < ntiles; it++) {
        int cur = it & 1;
        int nxt = cur ^ 1;

        // prefetch next tile (A to registers; B via cp.async straight to smem)
        float4 pa0, pa1, pb0, pb1;
        bool more = (it + 1) < ntiles;
        if (more) {
            int k0n = (it + 1) << 4;
            pa0 = fetchA(k0n, ar0, ac0);
            pa1 = fetchA(k0n, ar1, ac1);
            if (FULL) {
                cpB(nxt, k0n);
            } else {
                pb0 = fetchB(k0n, br0, bc0);
                pb1 = fetchB(k0n, br1, bc1);
            }
        }

        // compute on current buffer — split fragments: halves at +0 and +64
#pragma unroll
        for (int kk = 0; kk < 16; kk++) {
            float a[8], b[8];
            *(float4*)&a[0] = *(float4*)&As[cur][kk][tm * 4];
            *(float4*)&a[4] = *(float4*)&As[cur][kk][64 + tm * 4];
            *(float4*)&b[0] = *(float4*)&Bs[cur][kk][tn * 4];
            *(float4*)&b[4] = *(float4*)&Bs[cur][kk][64 + tn * 4];
#pragma unroll
            for (int i = 0; i < 8; i++)
#pragma unroll
                for (int j = 0; j < 8; j++) acc[i][j] = fmaf(a[i], b[j], acc[i][j]);
        }

        if (more) {
            storeA(nxt, pa0, pa1);
            if (!FULL) storeB(nxt, pb0, pb1);
        }
        if (FULL) cp_async_wait_all();
        __syncthreads();
    }

    // --- epilogue (split-fragment index mapping) ---
#pragma unroll
    for (int i = 0; i < 8; i++) {
        int mi = (i < 4) ? (tm * 4 + i) : (64 + tm * 4 + i - 4);
        int m = m0 + mi;
#pragma unroll
        for (int j = 0; j < 8; j++) {
            int nj = (j < 4) ? (tn * 4 + j) : (64 + tn * 4 + j - 4);
            int n = n0 + nj;
            if (FULL || n < N) {
                float v = acc[i][j] + bias[n];
                if (relu1) v = fmaxf(v, 0.f);
                if (hasres) {
                    v += res[(size_t)m * ldc + n];
                    v = fmaxf(v, 0.f);
                }
                C[(size_t)m * ldc + n] = v;
            }
        }
    }
}

// ---------------- attention: per (b,h), one query per thread, online softmax ----------------
// QKV packed: row stride 1536; q at +0, k at +512, v at +1024.
__global__ __launch_bounds__(256)
void attn_kernel(const float* __restrict__ QKV, float* __restrict__ O) {
    int bh = blockIdx.x;
    int b = bh >> 3, h = bh & 7;
    int tid = threadIdx.x;                 // query index n

    __shared__ float Ks[64][64];
    __shared__ float Vs[64][64];

    const float scale = 0.125f;            // 1/sqrt(64)
    float q[64];
    const float* qp = QKV + ((size_t)(b * NMAX_ + tid) * QKV_N) + h * 64;
#pragma unroll
    for (int i = 0; i < 16; i++) *(float4*)&q[i * 4] = *(const float4*)(qp + i * 4);

    float mrun = -1e30f, l = 0.f;
    float acc[64];
#pragma unroll
    for (int i = 0; i < 64; i++) acc[i] = 0.f;

    for (int kt = 0; kt < 4; kt++) {
        __syncthreads();
#pragma unroll
        for (int rep = 0; rep < 4; rep++) {
            int f = rep * 256 + tid;       // 0..1023
            int r = f >> 4;                // 0..63
            int c = (f & 15) * 4;
            size_t base = ((size_t)(b * NMAX_ + kt * 64 + r) * QKV_N) + h * 64 + c;
            *(float4*)&Ks[r][c] = *(const float4*)(QKV + base + DMODEL_);
            *(float4*)&Vs[r][c] = *(const float4*)(QKV + base + 2 * DMODEL_);
        }
        __syncthreads();
        for (int mm = 0; mm < 64; mm++) {
            float s = 0.f;
#pragma unroll
            for (int d = 0; d < 64; d++) s = fmaf(q[d], Ks[mm][d], s);
            s *= scale;
            if (s > mrun) {
                float corr = __expf(mrun - s);
                l = fmaf(l, corr, 1.f);
#pragma unroll
                for (int d = 0; d < 64; d++) acc[d] = fmaf(acc[d], corr, Vs[mm][d]);
                mrun = s;
            } else {
                float p = __expf(s - mrun);
                l += p;
#pragma unroll
                for (int d = 0; d < 64; d++) acc[d] = fmaf(p, Vs[mm][d], acc[d]);
            }
        }
    }
    float inv = 1.f / l;
    float* op = O + ((size_t)(b * NMAX_ + tid) * DMODEL_) + h * 64;
#pragma unroll
    for (int d = 0; d < 64; d++) op[d] = acc[d] * inv;
}

// ---------------- launch ----------------
extern "C" void kernel_launch(void* const* d_in, const int* in_sizes, int n_in,
                              void* d_out, int out_size) {
    const float* x      = (const float*)d_in[0];
    // d_in[1] = types (unused by the reference computation)
    const float* w_emb  = (const float*)d_in[2];
    const float* b_emb  = (const float*)d_in[3];
    const float* tcn_w1 = (const float*)d_in[4];
    const float* tcn_b1 = (const float*)d_in[5];
    const float* tcn_w2 = (const float*)d_in[6];
    const float* tcn_b2 = (const float*)d_in[7];
    const float* w_enc  = (const float*)d_in[8];
    const float* b_enc  = (const float*)d_in[9];
    const float* wq     = (const float*)d_in[10];
    const float* bq     = (const float*)d_in[11];
    const float* wk     = (const float*)d_in[12];
    const float* bk     = (const float*)d_in[13];
    const float* wv     = (const float*)d_in[14];
    const float* bv     = (const float*)d_in[15];
    const float* wo     = (const float*)d_in[16];
    const float* bo     = (const float*)d_in[17];
    const float* w_p1   = (const float*)d_in[18];
    const float* b_p1   = (const float*)d_in[19];
    const float* w_p2   = (const float*)d_in[20];
    const float* b_p2   = (const float*)d_in[21];
    const float* w_p3   = (const float*)d_in[22];
    const float* b_p3   = (const float*)d_in[23];
    float* out = (float*)d_out;

    float *h, *z, *feat, *qkv, *att, *o, *p1, *p2, *wc, *wqkv, *bqkv;
    int* mask;
    cudaGetSymbolAddress((void**)&h,    g_h);
    cudaGetSymbolAddress((void**)&z,    g_z);
    cudaGetSymbolAddress((void**)&feat, g_feat);
    cudaGetSymbolAddress((void**)&qkv,  g_qkv);
    cudaGetSymbolAddress((void**)&att,  g_att);
    cudaGetSymbolAddress((void**)&o,    g_o);
    cudaGetSymbolAddress((void**)&p1,   g_p1);
    cudaGetSymbolAddress((void**)&p2,   g_p2);
    cudaGetSymbolAddress((void**)&wc,   g_wc);
    cudaGetSymbolAddress((void**)&wqkv, g_wqkv);
    cudaGetSymbolAddress((void**)&bqkv, g_bqkv);
    cudaGetSymbolAddress((void**)&mask, g_mask);

    // 1) active mask + embedding + weight prep
    mask_kernel<<<B_, NMAX_>>>(x, mask);
    emb_kernel<<<(int)(((size_t)MROWS * E_ + 255) / 256), 256>>>(x, w_emb, b_emb, h);
    wprep_kernel<<<(6 * 49152 + 255) / 256, 256>>>(tcn_w1, tcn_w2, wc);
    qkvprep_kernel<<<(DMODEL_ * QKV_N + 255) / 256, 256>>>(wq, wk, wv, bq, bk, bv, wqkv, bqkv);

    // 2) TCN: 3 residual blocks (dil = 1,2,4); blocks of 8 inactive agents skipped
    for (int blk = 0; blk < 3; blk++) {
        int dil = 1 << blk;
        // z = relu(conv1(h))
        gemm_kernel<1, 1><<<dim3(MROWS / 128, 1), 256>>>(
            h, wc + (size_t)(blk * 2 + 0) * 49152, tcn_b1 + blk * 128, nullptr, z,
            128, 384, 0, 128, /*relu1=*/1, /*res=*/0, dil, mask);
        // h = relu(h + relu(conv2(z)))
        gemm_kernel<1, 1><<<dim3(MROWS / 128, 1), 256>>>(
            z, wc + (size_t)(blk * 2 + 1) * 49152, tcn_b2 + blk * 128, h, h,
            128, 384, 0, 128, /*relu1=*/1, /*res=*/1, dil, mask);
    }

    // 3) mask inactive agents, encoder GEMM (h rows are already [T*E] t-major)
    maskapply_kernel<<<BN_ROWS, 256>>>(h, mask);
    gemm_kernel<0, 1><<<dim3(BN_ROWS / 128, DMODEL_ / 128), 256>>>(
        h, w_enc, b_enc, nullptr, feat, DMODEL_, HROW, HROW, DMODEL_, 0, 0, 0, nullptr);

    // 4) fused QKV projection + attention + output projection
    gemm_kernel<0, 1><<<dim3(BN_ROWS / 128, QKV_N / 128), 256>>>(
        feat, wqkv, bqkv, nullptr, qkv, QKV_N, DMODEL_, DMODEL_, QKV_N, 0, 0, 0, nullptr);
    attn_kernel<<<B_ * 8, 256>>>(qkv, att);
    gemm_kernel<0, 1><<<dim3(BN_ROWS / 128, DMODEL_ / 128), 256>>>(
        att, wo, bo, nullptr, o, DMODEL_, DMODEL_, DMODEL_, DMODEL_, 0, 0, 0, nullptr);

    // 5) predictor MLP
    gemm_kernel<0, 1><<<dim3(BN_ROWS / 128, 1024 / 128), 256>>>(
        o, w_p1, b_p1, nullptr, p1, 1024, DMODEL_, DMODEL_, 1024, 1, 0, 0, nullptr);
    gemm_kernel<0, 1><<<dim3(BN_ROWS / 128, 1024 / 128), 256>>>(
        p1, w_p2, b_p2, nullptr, p2, 1024, 1024, 1024, 1024, 1, 0, 0, nullptr);
    gemm_kernel<0, 0><<<dim3(BN_ROWS / 128, 1), 256>>>(
        p2, w_p3, b_p3, nullptr, out, 24, 1024, 1024, 24, 0, 0, 0, nullptr);
}

// round 13
// speedup vs baseline: 1.3837x; 1.3837x over previous
#include <cuda_runtime.h>
#include <stdint.h>
#include <math.h>

// ---------------- dims ----------------
#define B_ 64
#define NMAX_ 256
#define TOBS_ 16
#define DIN_ 2
#define E_ 128
#define DMODEL_ 512
#define BN_ROWS (B_ * NMAX_)            // 16384
#define MROWS (BN_ROWS * TOBS_)         // 262144
#define HROW (TOBS_ * E_)               // 2048
#define QKV_N 1536

// ---------------- scratch (device globals; no runtime alloc) ----------------
__device__ float g_h[(size_t)BN_ROWS * HROW];    // [bn][t][e]
__device__ float g_z[(size_t)BN_ROWS * HROW];
__device__ float g_feat[(size_t)BN_ROWS * DMODEL_];   // compact rows
__device__ float g_qkv[(size_t)BN_ROWS * QKV_N];      // compact rows
__device__ float g_att[(size_t)BN_ROWS * DMODEL_];    // compact rows
__device__ float g_o[(size_t)BN_ROWS * DMODEL_];      // compact rows
__device__ float g_p1[(size_t)BN_ROWS * 1024];        // compact rows
__device__ float g_p2[(size_t)BN_ROWS * 1024];        // compact rows
__device__ float g_p3c[(size_t)BN_ROWS * 24];         // compact rows
__device__ float g_wc[6 * 384 * 128];            // [blk*2+conv][tap*128+i][o]
__device__ float g_wqkv[DMODEL_ * QKV_N];        // [k][ wq | wk | wv ]
__device__ float g_bqkv[QKV_N];
__device__ int   g_mask[BN_ROWS];
__device__ int   g_na[B_];
__device__ int   g_base[B_];
__device__ int   g_total;
__device__ int   g_row2bn[BN_ROWS];

// ---------------- cp.async helpers ----------------
__device__ __forceinline__ void cp_async16(uint32_t smem_addr, const void* gptr) {
    asm volatile("cp.async.cg.shared.global [%0], [%1], 16;\n"
                 :: "r"(smem_addr), "l"(gptr));
}
__device__ __forceinline__ void cp_async_commit() {
    asm volatile("cp.async.commit_group;\n" ::);
}
__device__ __forceinline__ void cp_async_wait_all() {
    asm volatile("cp.async.wait_group 0;\n" ::: "memory");
}

// ---------------- active-agent mask + per-scene count ----------------
__global__ void mask_kernel(const float* __restrict__ x, int* __restrict__ mask,
                            int* __restrict__ na) {
    int b = blockIdx.x;
    int n = threadIdx.x;
    const float* p = x + (size_t)(b * NMAX_ + n) * (TOBS_ * DIN_);
    float s = 0.f;
#pragma unroll
    for (int j = 0; j < TOBS_ * DIN_; j++) s += p[j];
    __shared__ int cnt;
    if (n == 0) cnt = 0;
    __syncthreads();
    if (s > 0.0f) atomicAdd(&cnt, 1);
    __syncthreads();
    mask[b * NMAX_ + n] = (n < cnt) ? 1 : 0;
    if (n == 0) na[b] = cnt;
}

// ---------------- scan: base[b], total (64 scenes, serial) ----------------
__global__ void scan_kernel(const int* __restrict__ na, int* __restrict__ base,
                            int* __restrict__ total) {
    if (threadIdx.x == 0 && blockIdx.x == 0) {
        int acc = 0;
        for (int b = 0; b < B_; b++) {
            base[b] = acc;
            acc += na[b] + (na[b] < NMAX_ ? 1 : 0);   // actives + 1 inactive rep
        }
        *total = acc;
    }
}

// ---------------- compact map: default 0 then scatter ----------------
__global__ void cmap_init_kernel(int* __restrict__ row2bn) {
    int i = blockIdx.x * blockDim.x + threadIdx.x;
    if (i < BN_ROWS) row2bn[i] = 0;
}
__global__ void cmap_fill_kernel(const int* __restrict__ na, const int* __restrict__ base,
                                 int* __restrict__ row2bn) {
    int bn = blockIdx.x * blockDim.x + threadIdx.x;
    if (bn >= BN_ROWS) return;
    int b = bn >> 8, n = bn & 255;
    if (n <= na[b] && (n < NMAX_)) {          // active prefix, plus agent==na as rep
        if (n < na[b] || na[b] < NMAX_)
            row2bn[base[b] + n] = bn;
    }
}

// ---------------- embedding: h[bn,t,e] = x0*w[0,e]+x1*w[1,e]+b[e] ----------------
__global__ void emb_kernel(const float* __restrict__ x, const float* __restrict__ w,
                           const float* __restrict__ bias, float* __restrict__ h) {
    size_t idx = (size_t)blockIdx.x * blockDim.x + threadIdx.x;
    if (idx >= (size_t)MROWS * E_) return;
    int e = (int)(idx & (E_ - 1));
    size_t row = idx >> 7;                 // bn*16+t
    float x0 = x[row * 2 + 0];
    float x1 = x[row * 2 + 1];
    h[idx] = fmaf(x0, w[e], fmaf(x1, w[E_ + e], bias[e]));
}

// ---------------- conv weight transform: w[o][i][tap] -> wc[kk=tap*128+i][o] ----------------
__global__ void wprep_kernel(const float* __restrict__ w1, const float* __restrict__ w2,
                             float* __restrict__ out) {
    int t = blockIdx.x * blockDim.x + threadIdx.x;
    if (t >= 6 * 49152) return;
    int bc = t / 49152;       // blk*2 + conv
    int r = t % 49152;        // kk*128 + o
    int kk = r >> 7;
    int o = r & 127;
    int tap = kk >> 7;
    int i = kk & 127;
    int blk = bc >> 1, conv = bc & 1;
    const float* src = conv ? w2 : w1;
    out[t] = src[(((size_t)(blk * 128 + o) * 128 + i) * 3) + tap];
}

// ---------------- QKV weight/bias packing: [512][1536] = wq|wk|wv ----------------
__global__ void qkvprep_kernel(const float* __restrict__ wq, const float* __restrict__ wk,
                               const float* __restrict__ wv,
                               const float* __restrict__ bq, const float* __restrict__ bk,
                               const float* __restrict__ bv,
                               float* __restrict__ wout, float* __restrict__ bout) {
    int t = blockIdx.x * blockDim.x + threadIdx.x;
    if (t < DMODEL_ * QKV_N) {
        int k = t / QKV_N;
        int n = t % QKV_N;
        int sel = n >> 9;              // 0:q 1:k 2:v
        int nn = n & 511;
        const float* src = (sel == 0) ? wq : (sel == 1) ? wk : wv;
        wout[t] = src[(size_t)k * DMODEL_ + nn];
    }
    if (t < QKV_N) {
        int sel = t >> 9;
        int nn = t & 511;
        bout[t] = (sel == 0) ? bq[nn] : (sel == 1) ? bk[nn] : bv[nn];
    }
}

// ---------------- zero inactive agent rows of h ----------------
__global__ void maskapply_kernel(float* __restrict__ h, const int* __restrict__ mask) {
    int bn = blockIdx.x;
    if (mask[bn]) return;
    float4 z = make_float4(0.f, 0.f, 0.f, 0.f);
    float4* p = (float4*)(h + (size_t)bn * HROW);
    p[threadIdx.x] = z;
    p[threadIdx.x + 256] = z;
}

// ---------------- generic tiled GEMM, double-buffered, split fragments ----------------
// BM=128, BN=128, BK=16; 8x8 acc/thread; 256 threads; cp.async B path (FULL).
// CONV=1: implicit-gemm gather over [bn][t][128] + dilation; all-inactive block skip.
// GATHER=1: A row index via row2bn (compact gather).
// d_total != nullptr: block exits if m0 >= *d_total (compact M bound).
template <int CONV, int FULL, int GATHER>
__global__ __launch_bounds__(256)
void gemm_kernel(const float* __restrict__ A, const float* __restrict__ Bm,
                 const float* __restrict__ bias, const float* __restrict__ res,
                 float* __restrict__ C,
                 int N, int Kdim, int lda, int ldc,
                 int relu1, int hasres, int dil,
                 const int* __restrict__ mask,
                 const int* __restrict__ row2bn,
                 const int* __restrict__ d_total) {
    int tid = threadIdx.x;
    int m0 = blockIdx.x * 128;
    int n0 = blockIdx.y * 128;

    if (d_total && m0 >= *d_total) return;

    if (CONV) {
        int bn0 = m0 >> 4;
        int any = 0;
#pragma unroll
        for (int i = 0; i < 8; i++) any |= mask[bn0 + i];
        if (!any) return;
    }

    __shared__ float As[2][16][128];
    __shared__ float Bs[2][16][128];

    int tm = tid >> 4;        // 0..15
    int tn = tid & 15;        // 0..15

    int ar0 = (tid) >> 2,        ac0 = ((tid) & 3) * 4;
    int ar1 = (256 + tid) >> 2,  ac1 = ((256 + tid) & 3) * 4;
    int br0 = (tid) >> 5,        bc0 = ((tid) & 31) * 4;
    int br1 = (256 + tid) >> 5,  bc1 = ((256 + tid) & 31) * 4;

    // precomputed A offsets (non-CONV)
    size_t aoff0 = 0, aoff1 = 0;
    if (!CONV) {
        int r0m = m0 + ar0, r1m = m0 + ar1;
        if (GATHER) { r0m = row2bn[r0m]; r1m = row2bn[r1m]; }
        aoff0 = (size_t)r0m * lda + ac0;
        aoff1 = (size_t)r1m * lda + ac1;
    }

    uint32_t bs0 = (uint32_t)__cvta_generic_to_shared(&Bs[0][br0][bc0]);
    uint32_t bs1 = (uint32_t)__cvta_generic_to_shared(&Bs[0][br1][bc1]);
    const uint32_t BUFB = 16 * 128 * 4;

    float acc[8][8];
#pragma unroll
    for (int i = 0; i < 8; i++)
#pragma unroll
        for (int j = 0; j < 8; j++) acc[i][j] = 0.f;

    int ntiles = Kdim >> 4;

    auto fetchA = [&](int k0, int r, int c4, size_t aoff) -> float4 {
        if (CONV) {
            int m = m0 + r;
            int bn = m >> 4, t = m & 15;
            int kk = k0 + c4;
            int tap = kk >> 7;
            int e = kk & 127;
            int tsrc = t - (2 - tap) * dil;
            if (tsrc >= 0)
                return *(const float4*)(A + (size_t)bn * HROW + tsrc * E_ + e);
            return make_float4(0.f, 0.f, 0.f, 0.f);
        }
        return *(const float4*)(A + aoff + k0);
    };
    auto storeA = [&](int buf, float4 a0, float4 a1) {
        As[buf][ac0 + 0][ar0] = a0.x;
        As[buf][ac0 + 1][ar0] = a0.y;
        As[buf][ac0 + 2][ar0] = a0.z;
        As[buf][ac0 + 3][ar0] = a0.w;
        As[buf][ac1 + 0][ar1] = a1.x;
        As[buf][ac1 + 1][ar1] = a1.y;
        As[buf][ac1 + 2][ar1] = a1.z;
        As[buf][ac1 + 3][ar1] = a1.w;
    };
    auto cpB = [&](int buf, int k0) {
        cp_async16(bs0 + buf * BUFB, Bm + (size_t)(k0 + br0) * N + (n0 + bc0));
        cp_async16(bs1 + buf * BUFB, Bm + (size_t)(k0 + br1) * N + (n0 + bc1));
        cp_async_commit();
    };
    auto fetchB = [&](int k0, int r, int c) -> float4 {
        int n = n0 + c;
        const float* bp = Bm + (size_t)(k0 + r) * N + n;
        if (n + 3 < N) return *(const float4*)bp;
        float4 v;
        v.x = (n + 0 < N) ? bp[0] : 0.f;
        v.y = (n + 1 < N) ? bp[1] : 0.f;
        v.z = (n + 2 < N) ? bp[2] : 0.f;
        v.w = (n + 3 < N) ? bp[3] : 0.f;
        return v;
    };
    auto storeB = [&](int buf, float4 b0, float4 b1) {
        *(float4*)&Bs[buf][br0][bc0] = b0;
        *(float4*)&Bs[buf][br1][bc1] = b1;
    };

    {
        float4 a0 = fetchA(0, ar0, ac0, aoff0);
        float4 a1 = fetchA(0, ar1, ac1, aoff1);
        storeA(0, a0, a1);
        if (FULL) {
            cpB(0, 0);
            cp_async_wait_all();
        } else {
            storeB(0, fetchB(0, br0, bc0), fetchB(0, br1, bc1));
        }
    }
    __syncthreads();

    for (int it = 0; it < ntiles; it++) {
        int cur = it & 1;
        int nxt = cur ^ 1;

        float4 pa0, pa1, pb0, pb1;
        bool more = (it + 1) < ntiles;
        if (more) {
            int k0n = (it + 1) << 4;
            pa0 = fetchA(k0n, ar0, ac0, aoff0);
            pa1 = fetchA(k0n, ar1, ac1, aoff1);
            if (FULL) {
                cpB(nxt, k0n);
            } else {
                pb0 = fetchB(k0n, br0, bc0);
                pb1 = fetchB(k0n, br1, bc1);
            }
        }

#pragma unroll
        for (int kk = 0; kk < 16; kk++) {
            float a[8], b[8];
            *(float4*)&a[0] = *(float4*)&As[cur][kk][tm * 4];
            *(float4*)&a[4] = *(float4*)&As[cur][kk][64 + tm * 4];
            *(float4*)&b[0] = *(float4*)&Bs[cur][kk][tn * 4];
            *(float4*)&b[4] = *(float4*)&Bs[cur][kk][64 + tn * 4];
#pragma unroll
            for (int i = 0; i < 8; i++)
#pragma unroll
                for (int j = 0; j < 8; j++) acc[i][j] = fmaf(a[i], b[j], acc[i][j]);
        }

        if (more) {
            storeA(nxt, pa0, pa1);
            if (!FULL) storeB(nxt, pb0, pb1);
        }
        if (FULL) cp_async_wait_all();
        __syncthreads();
    }

#pragma unroll
    for (int i = 0; i < 8; i++) {
        int mi = (i < 4) ? (tm * 4 + i) : (64 + tm * 4 + i - 4);
        int m = m0 + mi;
#pragma unroll
        for (int j = 0; j < 8; j++) {
            int nj = (j < 4) ? (tn * 4 + j) : (64 + tn * 4 + j - 4);
            int n = n0 + nj;
            if (FULL || n < N) {
                float v = acc[i][j] + bias[n];
                if (relu1) v = fmaxf(v, 0.f);
                if (hasres) {
                    v += res[(size_t)m * ldc + n];
                    v = fmaxf(v, 0.f);
                }
                C[(size_t)m * ldc + n] = v;
            }
        }
    }
}

// ---------------- attention over compact rows, rep key multiplicity ----------------
// QKV compact rows, stride 1536: q +0, k +512, v +1024. Scene b rows:
// [base[b], base[b]+rows), rows = na + (na<256). Key local index na (if na<256)
// is the inactive representative with multiplicity 256-na.
__global__ __launch_bounds__(256)
void attn_kernel(const float* __restrict__ QKV, float* __restrict__ O,
                 const int* __restrict__ na_, const int* __restrict__ base_) {
    int bh = blockIdx.x;
    int b = bh >> 3, h = bh & 7;
    int tid = threadIdx.x;

    int na = na_[b];
    int base = base_[b];
    int rows = na + (na < NMAX_ ? 1 : 0);

    __shared__ float Ks[64][64];
    __shared__ float Vs[64][64];

    const float scale = 0.125f;            // 1/sqrt(64)
    int qrow = base + (tid < rows ? tid : rows - 1);
    float q[64];
    const float* qp = QKV + ((size_t)qrow * QKV_N) + h * 64;
#pragma unroll
    for (int i = 0; i < 16; i++) *(float4*)&q[i * 4] = *(const float4*)(qp + i * 4);

    float mrun = -1e30f, l = 0.f;
    float acc[64];
#pragma unroll
    for (int i = 0; i < 64; i++) acc[i] = 0.f;

    int ntile = (rows + 63) >> 6;
    for (int kt = 0; kt < ntile; kt++) {
        __syncthreads();
#pragma unroll
        for (int rep = 0; rep < 4; rep++) {
            int f = rep * 256 + tid;       // 0..1023
            int r = f >> 4;                // 0..63
            int c = (f & 15) * 4;
            int kloc = kt * 64 + r;
            int krow = base + (kloc < rows ? kloc : rows - 1);
            size_t gi = ((size_t)krow * QKV_N) + h * 64 + c;
            *(float4*)&Ks[r][c] = *(const float4*)(QKV + gi + DMODEL_);
            *(float4*)&Vs[r][c] = *(const float4*)(QKV + gi + 2 * DMODEL_);
        }
        __syncthreads();
        int tmax = rows - kt * 64;
        if (tmax > 64) tmax = 64;
        for (int mm = 0; mm < tmax; mm++) {
            int kloc = kt * 64 + mm;
            float wf = (kloc == na) ? (float)(NMAX_ - na) : 1.f;
            float s = 0.f;
#pragma unroll
            for (int d = 0; d < 64; d++) s = fmaf(q[d], Ks[mm][d], s);
            s *= scale;
            if (s > mrun) {
                float corr = __expf(mrun - s);
                l = fmaf(l, corr, wf);
#pragma unroll
                for (int d = 0; d < 64; d++)
                    acc[d] = acc[d] * corr + wf * Vs[mm][d];
                mrun = s;
            } else {
                float p = __expf(s - mrun);
                float wp = wf * p;
                l += wp;
#pragma unroll
                for (int d = 0; d < 64; d++) acc[d] = fmaf(wp, Vs[mm][d], acc[d]);
            }
        }
    }
    if (tid < rows) {
        float inv = 1.f / l;
        float* op = O + ((size_t)(base + tid) * DMODEL_) + h * 64;
#pragma unroll
        for (int d = 0; d < 64; d++) op[d] = acc[d] * inv;
    }
}

// ---------------- scatter compact predictions to full output ----------------
__global__ void scatter_kernel(const float* __restrict__ p3c, float* __restrict__ out,
                               const int* __restrict__ na_, const int* __restrict__ base_) {
    int idx = blockIdx.x * blockDim.x + threadIdx.x;   // over 16384*24
    if (idx >= BN_ROWS * 24) return;
    int bn = idx / 24, j = idx - bn * 24;
    int b = bn >> 8, n = bn & 255;
    int nn = n < na_[b] ? n : na_[b];
    int c = base_[b] + nn;
    out[idx] = p3c[(size_t)c * 24 + j];
}

// ---------------- launch ----------------
extern "C" void kernel_launch(void* const* d_in, const int* in_sizes, int n_in,
                              void* d_out, int out_size) {
    const float* x      = (const float*)d_in[0];
    // d_in[1] = types (unused by the reference computation)
    const float* w_emb  = (const float*)d_in[2];
    const float* b_emb  = (const float*)d_in[3];
    const float* tcn_w1 = (const float*)d_in[4];
    const float* tcn_b1 = (const float*)d_in[5];
    const float* tcn_w2 = (const float*)d_in[6];
    const float* tcn_b2 = (const float*)d_in[7];
    const float* w_enc  = (const float*)d_in[8];
    const float* b_enc  = (const float*)d_in[9];
    const float* wq     = (const float*)d_in[10];
    const float* bq     = (const float*)d_in[11];
    const float* wk     = (const float*)d_in[12];
    const float* bk     = (const float*)d_in[13];
    const float* wv     = (const float*)d_in[14];
    const float* bv     = (const float*)d_in[15];
    const float* wo     = (const float*)d_in[16];
    const float* bo     = (const float*)d_in[17];
    const float* w_p1   = (const float*)d_in[18];
    const float* b_p1   = (const float*)d_in[19];
    const float* w_p2   = (const float*)d_in[20];
    const float* b_p2   = (const float*)d_in[21];
    const float* w_p3   = (const float*)d_in[22];
    const float* b_p3   = (const float*)d_in[23];
    float* out = (float*)d_out;

    float *h, *z, *feat, *qkv, *att, *o, *p1, *p2, *p3c, *wc, *wqkv, *bqkv;
    int *mask, *na, *base, *total, *row2bn;
    cudaGetSymbolAddress((void**)&h,      g_h);
    cudaGetSymbolAddress((void**)&z,      g_z);
    cudaGetSymbolAddress((void**)&feat,   g_feat);
    cudaGetSymbolAddress((void**)&qkv,    g_qkv);
    cudaGetSymbolAddress((void**)&att,    g_att);
    cudaGetSymbolAddress((void**)&o,      g_o);
    cudaGetSymbolAddress((void**)&p1,     g_p1);
    cudaGetSymbolAddress((void**)&p2,     g_p2);
    cudaGetSymbolAddress((void**)&p3c,    g_p3c);
    cudaGetSymbolAddress((void**)&wc,     g_wc);
    cudaGetSymbolAddress((void**)&wqkv,   g_wqkv);
    cudaGetSymbolAddress((void**)&bqkv,   g_bqkv);
    cudaGetSymbolAddress((void**)&mask,   g_mask);
    cudaGetSymbolAddress((void**)&na,     g_na);
    cudaGetSymbolAddress((void**)&base,   g_base);
    cudaGetSymbolAddress((void**)&total,  g_total);
    cudaGetSymbolAddress((void**)&row2bn, g_row2bn);

    // 1) mask + compaction metadata + embedding + weight prep
    mask_kernel<<<B_, NMAX_>>>(x, mask, na);
    scan_kernel<<<1, 32>>>(na, base, total);
    cmap_init_kernel<<<BN_ROWS / 256, 256>>>(row2bn);
    cmap_fill_kernel<<<BN_ROWS / 256, 256>>>(na, base, row2bn);
    emb_kernel<<<(int)(((size_t)MROWS * E_ + 255) / 256), 256>>>(x, w_emb, b_emb, h);
    wprep_kernel<<<(6 * 49152 + 255) / 256, 256>>>(tcn_w1, tcn_w2, wc);
    qkvprep_kernel<<<(DMODEL_ * QKV_N + 255) / 256, 256>>>(wq, wk, wv, bq, bk, bv, wqkv, bqkv);

    // 2) TCN: 3 residual blocks (dil = 1,2,4); all-inactive 8-agent blocks skipped
    for (int blk = 0; blk < 3; blk++) {
        int dil = 1 << blk;
        gemm_kernel<1, 1, 0><<<dim3(MROWS / 128, 1), 256>>>(
            h, wc + (size_t)(blk * 2 + 0) * 49152, tcn_b1 + blk * 128, nullptr, z,
            128, 384, 0, 128, 1, 0, dil, mask, nullptr, nullptr);
        gemm_kernel<1, 1, 0><<<dim3(MROWS / 128, 1), 256>>>(
            z, wc + (size_t)(blk * 2 + 1) * 49152, tcn_b2 + blk * 128, h, h,
            128, 384, 0, 128, 1, 1, dil, mask, nullptr, nullptr);
    }

    // 3) zero inactive h rows, then COMPACT encoder GEMM (gather via row2bn)
    maskapply_kernel<<<BN_ROWS, 256>>>(h, mask);
    gemm_kernel<0, 1, 1><<<dim3(BN_ROWS / 128, DMODEL_ / 128), 256>>>(
        h, w_enc, b_enc, nullptr, feat, DMODEL_, HROW, HROW, DMODEL_, 0, 0, 0,
        nullptr, row2bn, total);

    // 4) compact QKV + attention (rep-key multiplicity) + output projection
    gemm_kernel<0, 1, 0><<<dim3(BN_ROWS / 128, QKV_N / 128), 256>>>(
        feat, wqkv, bqkv, nullptr, qkv, QKV_N, DMODEL_, DMODEL_, QKV_N, 0, 0, 0,
        nullptr, nullptr, total);
    attn_kernel<<<B_ * 8, 256>>>(qkv, att, na, base);
    gemm_kernel<0, 1, 0><<<dim3(BN_ROWS / 128, DMODEL_ / 128), 256>>>(
        att, wo, bo, nullptr, o, DMODEL_, DMODEL_, DMODEL_, DMODEL_, 0, 0, 0,
        nullptr, nullptr, total);

    // 5) compact predictor MLP, then scatter to full output
    gemm_kernel<0, 1, 0><<<dim3(BN_ROWS / 128, 1024 / 128), 256>>>(
        o, w_p1, b_p1, nullptr, p1, 1024, DMODEL_, DMODEL_, 1024, 1, 0, 0,
        nullptr, nullptr, total);
    gemm_kernel<0, 1, 0><<<dim3(BN_ROWS / 128, 1024 / 128), 256>>>(
        p1, w_p2, b_p2, nullptr, p2, 1024, 1024, 1024, 1024, 1, 0, 0,
        nullptr, nullptr, total);
    gemm_kernel<0, 0, 0><<<dim3(BN_ROWS / 128, 1), 256>>>(
        p2, w_p3, b_p3, nullptr, p3c, 24, 1024, 1024, 24, 0, 0, 0,
        nullptr, nullptr, total);
    scatter_kernel<<<(BN_ROWS * 24 + 255) / 256, 256>>>(p3c, out, na, base);
}

// round 14
// speedup vs baseline: 2.6563x; 1.9197x over previous
#include <cuda_runtime.h>
#include <stdint.h>
#include <math.h>

// ---------------- dims ----------------
#define B_ 64
#define NMAX_ 256
#define TOBS_ 16
#define DIN_ 2
#define E_ 128
#define DMODEL_ 512
#define BN_ROWS (B_ * NMAX_)            // 16384
#define MROWS (BN_ROWS * TOBS_)         // 262144
#define HROW (TOBS_ * E_)               // 2048
#define QKV_N 1536
#define SMP 136                         // padded smem row stride (conflict-free frags)

// ---------------- scratch (device globals; no runtime alloc) ----------------
__device__ float g_h[(size_t)BN_ROWS * HROW];    // [bn][t][e]
__device__ float g_z[(size_t)BN_ROWS * HROW];
__device__ float g_feat[(size_t)BN_ROWS * DMODEL_];   // compact rows
__device__ float g_qkv[(size_t)BN_ROWS * QKV_N];      // compact rows
__device__ float g_att[(size_t)BN_ROWS * DMODEL_];    // compact rows
__device__ float g_o[(size_t)BN_ROWS * DMODEL_];      // compact rows
__device__ float g_p1[(size_t)BN_ROWS * 1024];        // compact rows
__device__ float g_p2[(size_t)BN_ROWS * 1024];        // compact rows
__device__ float g_p3c[(size_t)BN_ROWS * 24];         // compact rows
__device__ float g_wc[6 * 384 * 128];            // [blk*2+conv][tap*128+i][o]
__device__ float g_wqkv[DMODEL_ * QKV_N];        // [k][ wq | wk | wv ]
__device__ float g_bqkv[QKV_N];
__device__ int   g_mask[BN_ROWS];
__device__ int   g_na[B_];
__device__ int   g_base[B_];
__device__ int   g_total;
__device__ int   g_row2bn[BN_ROWS];

// ---------------- helpers ----------------
__device__ __forceinline__ void cp_async16(uint32_t smem_addr, const void* gptr) {
    asm volatile("cp.async.cg.shared.global [%0], [%1], 16;\n"
                 :: "r"(smem_addr), "l"(gptr));
}
__device__ __forceinline__ void cp_async_commit() {
    asm volatile("cp.async.commit_group;\n" ::);
}
__device__ __forceinline__ void cp_async_wait_all() {
    asm volatile("cp.async.wait_group 0;\n" ::: "memory");
}
__device__ __forceinline__ uint32_t f2tf32(float f) {
    uint32_t r;
    asm("cvt.rna.tf32.f32 %0, %1;" : "=r"(r) : "f"(f));
    return r;
}
__device__ __forceinline__ void mma_tf32(float* c, const uint32_t* a, const uint32_t* b) {
    asm volatile(
        "mma.sync.aligned.m16n8k8.row.col.f32.tf32.tf32.f32 "
        "{%0,%1,%2,%3}, {%4,%5,%6,%7}, {%8,%9}, {%0,%1,%2,%3};"
        : "+f"(c[0]), "+f"(c[1]), "+f"(c[2]), "+f"(c[3])
        : "r"(a[0]), "r"(a[1]), "r"(a[2]), "r"(a[3]), "r"(b[0]), "r"(b[1]));
}

// ---------------- active-agent mask + per-scene count ----------------
__global__ void mask_kernel(const float* __restrict__ x, int* __restrict__ mask,
                            int* __restrict__ na) {
    int b = blockIdx.x;
    int n = threadIdx.x;
    const float* p = x + (size_t)(b * NMAX_ + n) * (TOBS_ * DIN_);
    float s = 0.f;
#pragma unroll
    for (int j = 0; j < TOBS_ * DIN_; j++) s += p[j];
    __shared__ int cnt;
    if (n == 0) cnt = 0;
    __syncthreads();
    if (s > 0.0f) atomicAdd(&cnt, 1);
    __syncthreads();
    mask[b * NMAX_ + n] = (n < cnt) ? 1 : 0;
    if (n == 0) na[b] = cnt;
}

// ---------------- scan: base[b], total ----------------
__global__ void scan_kernel(const int* __restrict__ na, int* __restrict__ base,
                            int* __restrict__ total) {
    if (threadIdx.x == 0 && blockIdx.x == 0) {
        int acc = 0;
        for (int b = 0; b < B_; b++) {
            base[b] = acc;
            acc += na[b] + (na[b] < NMAX_ ? 1 : 0);
        }
        *total = acc;
    }
}

// ---------------- compact map ----------------
__global__ void cmap_init_kernel(int* __restrict__ row2bn) {
    int i = blockIdx.x * blockDim.x + threadIdx.x;
    if (i < BN_ROWS) row2bn[i] = 0;
}
__global__ void cmap_fill_kernel(const int* __restrict__ na, const int* __restrict__ base,
                                 int* __restrict__ row2bn) {
    int bn = blockIdx.x * blockDim.x + threadIdx.x;
    if (bn >= BN_ROWS) return;
    int b = bn >> 8, n = bn & 255;
    if (n <= na[b] && (n < NMAX_)) {
        if (n < na[b] || na[b] < NMAX_)
            row2bn[base[b] + n] = bn;
    }
}

// ---------------- embedding ----------------
__global__ void emb_kernel(const float* __restrict__ x, const float* __restrict__ w,
                           const float* __restrict__ bias, float* __restrict__ h) {
    size_t idx = (size_t)blockIdx.x * blockDim.x + threadIdx.x;
    if (idx >= (size_t)MROWS * E_) return;
    int e = (int)(idx & (E_ - 1));
    size_t row = idx >> 7;
    float x0 = x[row * 2 + 0];
    float x1 = x[row * 2 + 1];
    h[idx] = fmaf(x0, w[e], fmaf(x1, w[E_ + e], bias[e]));
}

// ---------------- conv weight transform ----------------
__global__ void wprep_kernel(const float* __restrict__ w1, const float* __restrict__ w2,
                             float* __restrict__ out) {
    int t = blockIdx.x * blockDim.x + threadIdx.x;
    if (t >= 6 * 49152) return;
    int bc = t / 49152;
    int r = t % 49152;
    int kk = r >> 7;
    int o = r & 127;
    int tap = kk >> 7;
    int i = kk & 127;
    int blk = bc >> 1, conv = bc & 1;
    const float* src = conv ? w2 : w1;
    out[t] = src[(((size_t)(blk * 128 + o) * 128 + i) * 3) + tap];
}

// ---------------- QKV weight/bias packing ----------------
__global__ void qkvprep_kernel(const float* __restrict__ wq, const float* __restrict__ wk,
                               const float* __restrict__ wv,
                               const float* __restrict__ bq, const float* __restrict__ bk,
                               const float* __restrict__ bv,
                               float* __restrict__ wout, float* __restrict__ bout) {
    int t = blockIdx.x * blockDim.x + threadIdx.x;
    if (t < DMODEL_ * QKV_N) {
        int k = t / QKV_N;
        int n = t % QKV_N;
        int sel = n >> 9;
        int nn = n & 511;
        const float* src = (sel == 0) ? wq : (sel == 1) ? wk : wv;
        wout[t] = src[(size_t)k * DMODEL_ + nn];
    }
    if (t < QKV_N) {
        int sel = t >> 9;
        int nn = t & 511;
        bout[t] = (sel == 0) ? bq[nn] : (sel == 1) ? bk[nn] : bv[nn];
    }
}

// ---------------- zero inactive agent rows of h ----------------
__global__ void maskapply_kernel(float* __restrict__ h, const int* __restrict__ mask) {
    int bn = blockIdx.x;
    if (mask[bn]) return;
    float4 z = make_float4(0.f, 0.f, 0.f, 0.f);
    float4* p = (float4*)(h + (size_t)bn * HROW);
    p[threadIdx.x] = z;
    p[threadIdx.x + 256] = z;
}

// ================= tf32 tensor-core GEMM (mma.sync m16n8k8) =================
// BM=128, BN=128, BK=16; 8 warps: warp_m=wid&3 (32 rows), warp_n=wid>>2 (64 cols).
// A: register-staged -> smem (tf32-rounded at store), As[k][m], stride SMP.
// B: cp.async fp32 -> smem; tf32-rounded at fragment load. N must be %128==0.
// CONV=1: implicit-gemm gather (TCN) + all-inactive 8-agent block skip.
// GATHER=1: A rows via row2bn. d_total: compact M bound.
template <int CONV, int GATHER>
__global__ __launch_bounds__(256)
void tgemm_kernel(const float* __restrict__ A, const float* __restrict__ Bm,
                  const float* __restrict__ bias, const float* __restrict__ res,
                  float* __restrict__ C,
                  int N, int Kdim, int lda, int ldc,
                  int relu1, int hasres, int dil,
                  const int* __restrict__ mask,
                  const int* __restrict__ row2bn,
                  const int* __restrict__ d_total) {
    int tid = threadIdx.x;
    int m0 = blockIdx.x * 128;
    int n0 = blockIdx.y * 128;

    if (d_total && m0 >= *d_total) return;
    if (CONV) {
        int bn0 = m0 >> 4;
        int any = 0;
#pragma unroll
        for (int i = 0; i < 8; i++) any |= mask[bn0 + i];
        if (!any) return;
    }

    __shared__ float As[2][16][SMP];
    __shared__ float Bs[2][16][SMP];

    int lane = tid & 31;
    int wid = tid >> 5;
    int warp_m = wid & 3;          // 0..3 -> 32 rows each
    int warp_n = wid >> 2;         // 0..1 -> 64 cols each
    int lg = lane >> 2;            // groupID 0..7
    int lt = lane & 3;             // thread-in-group 0..3

    // loader coordinates (same as SIMT version)
    int ar0 = (tid) >> 2,        ac0 = ((tid) & 3) * 4;
    int ar1 = (256 + tid) >> 2,  ac1 = ((256 + tid) & 3) * 4;
    int br0 = (tid) >> 5,        bc0 = ((tid) & 31) * 4;
    int br1 = (256 + tid) >> 5,  bc1 = ((256 + tid) & 31) * 4;

    size_t aoff0 = 0, aoff1 = 0;
    if (!CONV) {
        int r0m = m0 + ar0, r1m = m0 + ar1;
        if (GATHER) { r0m = row2bn[r0m]; r1m = row2bn[r1m]; }
        aoff0 = (size_t)r0m * lda + ac0;
        aoff1 = (size_t)r1m * lda + ac1;
    }

    uint32_t bs0 = (uint32_t)__cvta_generic_to_shared(&Bs[0][br0][bc0]);
    uint32_t bs1 = (uint32_t)__cvta_generic_to_shared(&Bs[0][br1][bc1]);
    const uint32_t BUFB = 16 * SMP * 4;

    float acc[2][8][4];
#pragma unroll
    for (int i = 0; i < 2; i++)
#pragma unroll
        for (int j = 0; j < 8; j++)
#pragma unroll
            for (int k = 0; k < 4; k++) acc[i][j][k] = 0.f;

    int ntiles = Kdim >> 4;

    auto fetchA = [&](int k0, int r, int c4, size_t aoff) -> float4 {
        if (CONV) {
            int m = m0 + r;
            int bn = m >> 4, t = m & 15;
            int kk = k0 + c4;
            int tap = kk >> 7;
            int e = kk & 127;
            int tsrc = t - (2 - tap) * dil;
            if (tsrc >= 0)
                return *(const float4*)(A + (size_t)bn * HROW + tsrc * E_ + e);
            return make_float4(0.f, 0.f, 0.f, 0.f);
        }
        return *(const float4*)(A + aoff + k0);
    };
    auto storeA = [&](int buf, float4 a0, float4 a1) {
        As[buf][ac0 + 0][ar0] = __uint_as_float(f2tf32(a0.x));
        As[buf][ac0 + 1][ar0] = __uint_as_float(f2tf32(a0.y));
        As[buf][ac0 + 2][ar0] = __uint_as_float(f2tf32(a0.z));
        As[buf][ac0 + 3][ar0] = __uint_as_float(f2tf32(a0.w));
        As[buf][ac1 + 0][ar1] = __uint_as_float(f2tf32(a1.x));
        As[buf][ac1 + 1][ar1] = __uint_as_float(f2tf32(a1.y));
        As[buf][ac1 + 2][ar1] = __uint_as_float(f2tf32(a1.z));
        As[buf][ac1 + 3][ar1] = __uint_as_float(f2tf32(a1.w));
    };
    auto cpB = [&](int buf, int k0) {
        cp_async16(bs0 + buf * BUFB, Bm + (size_t)(k0 + br0) * N + (n0 + bc0));
        cp_async16(bs1 + buf * BUFB, Bm + (size_t)(k0 + br1) * N + (n0 + bc1));
        cp_async_commit();
    };

    // prologue
    {
        float4 a0 = fetchA(0, ar0, ac0, aoff0);
        float4 a1 = fetchA(0, ar1, ac1, aoff1);
        storeA(0, a0, a1);
        cpB(0, 0);
        cp_async_wait_all();
    }
    __syncthreads();

    for (int it = 0; it < ntiles; it++) {
        int cur = it & 1;
        int nxt = cur ^ 1;

        float4 pa0, pa1;
        bool more = (it + 1) < ntiles;
        if (more) {
            int k0n = (it + 1) << 4;
            pa0 = fetchA(k0n, ar0, ac0, aoff0);
            pa1 = fetchA(k0n, ar1, ac1, aoff1);
            cpB(nxt, k0n);
        }

        // two k-chunks of 8
#pragma unroll
        for (int kc = 0; kc < 16; kc += 8) {
            uint32_t afr[2][4];
#pragma unroll
            for (int mt = 0; mt < 2; mt++) {
                int r0 = warp_m * 32 + mt * 16 + lg;
                afr[mt][0] = __float_as_uint(As[cur][kc + lt][r0]);
                afr[mt][1] = __float_as_uint(As[cur][kc + lt][r0 + 8]);
                afr[mt][2] = __float_as_uint(As[cur][kc + lt + 4][r0]);
                afr[mt][3] = __float_as_uint(As[cur][kc + lt + 4][r0 + 8]);
            }
            uint32_t bfr[8][2];
#pragma unroll
            for (int nt = 0; nt < 8; nt++) {
                int nn = warp_n * 64 + nt * 8 + lg;
                bfr[nt][0] = f2tf32(Bs[cur][kc + lt][nn]);
                bfr[nt][1] = f2tf32(Bs[cur][kc + lt + 4][nn]);
            }
#pragma unroll
            for (int mt = 0; mt < 2; mt++)
#pragma unroll
                for (int nt = 0; nt < 8; nt++)
                    mma_tf32(acc[mt][nt], afr[mt], bfr[nt]);
        }

        if (more) storeA(nxt, pa0, pa1);
        cp_async_wait_all();
        __syncthreads();
    }

    // epilogue: c0/c1 at (row, col), (row, col+1); c2/c3 at row+8
#pragma unroll
    for (int mt = 0; mt < 2; mt++) {
        int rm = m0 + warp_m * 32 + mt * 16 + lg;
#pragma unroll
        for (int nt = 0; nt < 8; nt++) {
            int n = n0 + warp_n * 64 + nt * 8 + lt * 2;
#pragma unroll
            for (int half = 0; half < 2; half++) {
                int m = rm + half * 8;
                float v0 = acc[mt][nt][half * 2 + 0] + bias[n];
                float v1 = acc[mt][nt][half * 2 + 1] + bias[n + 1];
                if (relu1) { v0 = fmaxf(v0, 0.f); v1 = fmaxf(v1, 0.f); }
                if (hasres) {
                    v0 += res[(size_t)m * ldc + n];
                    v1 += res[(size_t)m * ldc + n + 1];
                    v0 = fmaxf(v0, 0.f);
                    v1 = fmaxf(v1, 0.f);
                }
                float2 v2 = make_float2(v0, v1);
                *(float2*)(C + (size_t)m * ldc + n) = v2;
            }
        }
    }
}

// ---------------- small SIMT GEMM (final N=24 projection) ----------------
__global__ __launch_bounds__(256)
void gemm_small_kernel(const float* __restrict__ A, const float* __restrict__ Bm,
                       const float* __restrict__ bias, float* __restrict__ C,
                       int N, int Kdim, int lda, int ldc,
                       const int* __restrict__ d_total) {
    int tid = threadIdx.x;
    int m0 = blockIdx.x * 128;
    if (d_total && m0 >= *d_total) return;

    __shared__ float As[16][128];
    __shared__ float Bs[16][32];

    int tm = tid >> 4;   // 0..15
    int tn = tid & 15;   // 0..15 (cols 0..23 used, 2 cols/thread: tn*2, tn*2+1... use 16x? )
    // 8 m-rows x 2 n-cols per thread (N=24 -> threads tn<12 active for cols)
    float acc[8][2];
#pragma unroll
    for (int i = 0; i < 8; i++) { acc[i][0] = 0.f; acc[i][1] = 0.f; }

    for (int k0 = 0; k0 < Kdim; k0 += 16) {
        // A tile 128x16
#pragma unroll
        for (int rep = 0; rep < 2; rep++) {
            int f = rep * 256 + tid;
            int r = f >> 2;
            int c4 = (f & 3) * 4;
            float4 v = *(const float4*)(A + (size_t)(m0 + r) * lda + k0 + c4);
            As[c4 + 0][r] = v.x;
            As[c4 + 1][r] = v.y;
            As[c4 + 2][r] = v.z;
            As[c4 + 3][r] = v.w;
        }
        // B tile 16x24 (pad to 32)
        if (tid < 16 * 8) {
            int r = tid >> 3;
            int c = (tid & 7) * 4;
            float4 v;
            const float* bp = Bm + (size_t)(k0 + r) * N + c;
            v.x = (c + 0 < N) ? bp[0] : 0.f;
            v.y = (c + 1 < N) ? bp[1] : 0.f;
            v.z = (c + 2 < N) ? bp[2] : 0.f;
            v.w = (c + 3 < N) ? bp[3] : 0.f;
            *(float4*)&Bs[r][c] = v;
        }
        __syncthreads();
#pragma unroll
        for (int kk = 0; kk < 16; kk++) {
            float a[8];
            *(float4*)&a[0] = *(float4*)&As[kk][tm * 8];
            *(float4*)&a[4] = *(float4*)&As[kk][tm * 8 + 4];
            float b0 = Bs[kk][tn * 2], b1 = Bs[kk][tn * 2 + 1];
#pragma unroll
            for (int i = 0; i < 8; i++) {
                acc[i][0] = fmaf(a[i], b0, acc[i][0]);
                acc[i][1] = fmaf(a[i], b1, acc[i][1]);
            }
        }
        __syncthreads();
    }
#pragma unroll
    for (int i = 0; i < 8; i++) {
        int m = m0 + tm * 8 + i;
#pragma unroll
        for (int j = 0; j < 2; j++) {
            int n = tn * 2 + j;
            if (n < N)
                C[(size_t)m * ldc + n] = acc[i][j] + bias[n];
        }
    }
}

// ---------------- attention over compact rows, rep key multiplicity ----------------
__global__ __launch_bounds__(256)
void attn_kernel(const float* __restrict__ QKV, float* __restrict__ O,
                 const int* __restrict__ na_, const int* __restrict__ base_) {
    int bh = blockIdx.x;
    int b = bh >> 3, h = bh & 7;
    int tid = threadIdx.x;

    int na = na_[b];
    int base = base_[b];
    int rows = na + (na < NMAX_ ? 1 : 0);

    __shared__ float Ks[64][64];
    __shared__ float Vs[64][64];

    const float scale = 0.125f;
    int qrow = base + (tid < rows ? tid : rows - 1);
    float q[64];
    const float* qp = QKV + ((size_t)qrow * QKV_N) + h * 64;
#pragma unroll
    for (int i = 0; i < 16; i++) *(float4*)&q[i * 4] = *(const float4*)(qp + i * 4);

    float mrun = -1e30f, l = 0.f;
    float acc[64];
#pragma unroll
    for (int i = 0; i < 64; i++) acc[i] = 0.f;

    int ntile = (rows + 63) >> 6;
    for (int kt = 0; kt < ntile; kt++) {
        __syncthreads();
#pragma unroll
        for (int rep = 0; rep < 4; rep++) {
            int f = rep * 256 + tid;
            int r = f >> 4;
            int c = (f & 15) * 4;
            int kloc = kt * 64 + r;
            int krow = base + (kloc < rows ? kloc : rows - 1);
            size_t gi = ((size_t)krow * QKV_N) + h * 64 + c;
            *(float4*)&Ks[r][c] = *(const float4*)(QKV + gi + DMODEL_);
            *(float4*)&Vs[r][c] = *(const float4*)(QKV + gi + 2 * DMODEL_);
        }
        __syncthreads();
        int tmax = rows - kt * 64;
        if (tmax > 64) tmax = 64;
        for (int mm = 0; mm < tmax; mm++) {
            int kloc = kt * 64 + mm;
            float wf = (kloc == na) ? (float)(NMAX_ - na) : 1.f;
            float s = 0.f;
#pragma unroll
            for (int d = 0; d < 64; d++) s = fmaf(q[d], Ks[mm][d], s);
            s *= scale;
            if (s > mrun) {
                float corr = __expf(mrun - s);
                l = fmaf(l, corr, wf);
#pragma unroll
                for (int d = 0; d < 64; d++)
                    acc[d] = acc[d] * corr + wf * Vs[mm][d];
                mrun = s;
            } else {
                float p = __expf(s - mrun);
                float wp = wf * p;
                l += wp;
#pragma unroll
                for (int d = 0; d < 64; d++) acc[d] = fmaf(wp, Vs[mm][d], acc[d]);
            }
        }
    }
    if (tid < rows) {
        float inv = 1.f / l;
        float* op = O + ((size_t)(base + tid) * DMODEL_) + h * 64;
#pragma unroll
        for (int d = 0; d < 64; d++) op[d] = acc[d] * inv;
    }
}

// ---------------- scatter compact predictions to full output ----------------
__global__ void scatter_kernel(const float* __restrict__ p3c, float* __restrict__ out,
                               const int* __restrict__ na_, const int* __restrict__ base_) {
    int idx = blockIdx.x * blockDim.x + threadIdx.x;
    if (idx >= BN_ROWS * 24) return;
    int bn = idx / 24, j = idx - bn * 24;
    int b = bn >> 8, n = bn & 255;
    int nn = n < na_[b] ? n : na_[b];
    int c = base_[b] + nn;
    out[idx] = p3c[(size_t)c * 24 + j];
}

// ---------------- launch ----------------
extern "C" void kernel_launch(void* const* d_in, const int* in_sizes, int n_in,
                              void* d_out, int out_size) {
    const float* x      = (const float*)d_in[0];
    const float* w_emb  = (const float*)d_in[2];
    const float* b_emb  = (const float*)d_in[3];
    const float* tcn_w1 = (const float*)d_in[4];
    const float* tcn_b1 = (const float*)d_in[5];
    const float* tcn_w2 = (const float*)d_in[6];
    const float* tcn_b2 = (const float*)d_in[7];
    const float* w_enc  = (const float*)d_in[8];
    const float* b_enc  = (const float*)d_in[9];
    const float* wq     = (const float*)d_in[10];
    const float* bq     = (const float*)d_in[11];
    const float* wk     = (const float*)d_in[12];
    const float* bk     = (const float*)d_in[13];
    const float* wv     = (const float*)d_in[14];
    const float* bv     = (const float*)d_in[15];
    const float* wo     = (const float*)d_in[16];
    const float* bo     = (const float*)d_in[17];
    const float* w_p1   = (const float*)d_in[18];
    const float* b_p1   = (const float*)d_in[19];
    const float* w_p2   = (const float*)d_in[20];
    const float* b_p2   = (const float*)d_in[21];
    const float* w_p3   = (const float*)d_in[22];
    const float* b_p3   = (const float*)d_in[23];
    float* out = (float*)d_out;

    float *h, *z, *feat, *qkv, *att, *o, *p1, *p2, *p3c, *wc, *wqkv, *bqkv;
    int *mask, *na, *base, *total, *row2bn;
    cudaGetSymbolAddress((void**)&h,      g_h);
    cudaGetSymbolAddress((void**)&z,      g_z);
    cudaGetSymbolAddress((void**)&feat,   g_feat);
    cudaGetSymbolAddress((void**)&qkv,    g_qkv);
    cudaGetSymbolAddress((void**)&att,    g_att);
    cudaGetSymbolAddress((void**)&o,      g_o);
    cudaGetSymbolAddress((void**)&p1,     g_p1);
    cudaGetSymbolAddress((void**)&p2,     g_p2);
    cudaGetSymbolAddress((void**)&p3c,    g_p3c);
    cudaGetSymbolAddress((void**)&wc,     g_wc);
    cudaGetSymbolAddress((void**)&wqkv,   g_wqkv);
    cudaGetSymbolAddress((void**)&bqkv,   g_bqkv);
    cudaGetSymbolAddress((void**)&mask,   g_mask);
    cudaGetSymbolAddress((void**)&na,     g_na);
    cudaGetSymbolAddress((void**)&base,   g_base);
    cudaGetSymbolAddress((void**)&total,  g_total);
    cudaGetSymbolAddress((void**)&row2bn, g_row2bn);

    // 1) mask + compaction metadata + embedding + weight prep
    mask_kernel<<<B_, NMAX_>>>(x, mask, na);
    scan_kernel<<<1, 32>>>(na, base, total);
    cmap_init_kernel<<<BN_ROWS / 256, 256>>>(row2bn);
    cmap_fill_kernel<<<BN_ROWS / 256, 256>>>(na, base, row2bn);
    emb_kernel<<<(int)(((size_t)MROWS * E_ + 255) / 256), 256>>>(x, w_emb, b_emb, h);
    wprep_kernel<<<(6 * 49152 + 255) / 256, 256>>>(tcn_w1, tcn_w2, wc);
    qkvprep_kernel<<<(DMODEL_ * QKV_N + 255) / 256, 256>>>(wq, wk, wv, bq, bk, bv, wqkv, bqkv);

    // 2) TCN: 3 residual blocks (dil = 1,2,4); tf32 tensor path, inactive blocks skipped
    for (int blk = 0; blk < 3; blk++) {
        int dil = 1 << blk;
        tgemm_kernel<1, 0><<<dim3(MROWS / 128, 1), 256>>>(
            h, wc + (size_t)(blk * 2 + 0) * 49152, tcn_b1 + blk * 128, nullptr, z,
            128, 384, 0, 128, 1, 0, dil, mask, nullptr, nullptr);
        tgemm_kernel<1, 0><<<dim3(MROWS / 128, 1), 256>>>(
            z, wc + (size_t)(blk * 2 + 1) * 49152, tcn_b2 + blk * 128, h, h,
            128, 384, 0, 128, 1, 1, dil, mask, nullptr, nullptr);
    }

    // 3) zero inactive h rows, then COMPACT encoder GEMM (gather via row2bn)
    maskapply_kernel<<<BN_ROWS, 256>>>(h, mask);
    tgemm_kernel<0, 1><<<dim3(BN_ROWS / 128, DMODEL_ / 128), 256>>>(
        h, w_enc, b_enc, nullptr, feat, DMODEL_, HROW, HROW, DMODEL_, 0, 0, 0,
        nullptr, row2bn, total);

    // 4) compact QKV + attention + output projection
    tgemm_kernel<0, 0><<<dim3(BN_ROWS / 128, QKV_N / 128), 256>>>(
        feat, wqkv, bqkv, nullptr, qkv, QKV_N, DMODEL_, DMODEL_, QKV_N, 0, 0, 0,
        nullptr, nullptr, total);
    attn_kernel<<<B_ * 8, 256>>>(qkv, att, na, base);
    tgemm_kernel<0, 0><<<dim3(BN_ROWS / 128, DMODEL_ / 128), 256>>>(
        att, wo, bo, nullptr, o, DMODEL_, DMODEL_, DMODEL_, DMODEL_, 0, 0, 0,
        nullptr, nullptr, total);

    // 5) compact predictor MLP, then scatter to full output
    tgemm_kernel<0, 0><<<dim3(BN_ROWS / 128, 1024 / 128), 256>>>(
        o, w_p1, b_p1, nullptr, p1, 1024, DMODEL_, DMODEL_, 1024, 1, 0, 0,
        nullptr, nullptr, total);
    tgemm_kernel<0, 0><<<dim3(BN_ROWS / 128, 1024 / 128), 256>>>(
        p1, w_p2, b_p2, nullptr, p2, 1024, 1024, 1024, 1024, 1, 0, 0,
        nullptr, nullptr, total);
    gemm_small_kernel<<<BN_ROWS / 128, 256>>>(
        p2, w_p3, b_p3, p3c, 24, 1024, 1024, 24, total);
    scatter_kernel<<<(BN_ROWS * 24 + 255) / 256, 256>>>(p3c, out, na, base);
}

// round 17
// speedup vs baseline: 2.7377x; 1.0306x over previous
#include <cuda_runtime.h>
#include <stdint.h>
#include <math.h>

// ---------------- dims ----------------
#define B_ 64
#define NMAX_ 256
#define TOBS_ 16
#define DIN_ 2
#define E_ 128
#define DMODEL_ 512
#define BN_ROWS (B_ * NMAX_)            // 16384
#define MROWS (BN_ROWS * TOBS_)         // 262144
#define HROW (TOBS_ * E_)               // 2048
#define QKV_N 1536
#define SMP 136                         // padded smem row stride (conflict-free frags)

// ---------------- scratch (device globals; no runtime alloc) ----------------
__device__ float g_h[(size_t)BN_ROWS * HROW];    // [bn][t][e]
__device__ float g_z[(size_t)BN_ROWS * HROW];
__device__ float g_feat[(size_t)BN_ROWS * DMODEL_];   // compact rows
__device__ float g_qkv[(size_t)BN_ROWS * QKV_N];      // compact rows
__device__ float g_att[(size_t)BN_ROWS * DMODEL_];    // compact rows
__device__ float g_o[(size_t)BN_ROWS * DMODEL_];      // compact rows
__device__ float g_p1[(size_t)BN_ROWS * 1024];        // compact rows
__device__ float g_p2[(size_t)BN_ROWS * 1024];        // compact rows
__device__ float g_p3c[(size_t)BN_ROWS * 24];         // compact rows
__device__ float g_wc[6 * 384 * 128];            // tf32-rounded conv weights
__device__ float g_wqkv[DMODEL_ * QKV_N];        // tf32-rounded [k][ wq | wk | wv ]
__device__ float g_bqkv[QKV_N];
__device__ float g_wenc[HROW * DMODEL_];         // tf32-rounded w_enc
__device__ float g_wo[DMODEL_ * DMODEL_];        // tf32-rounded wo
__device__ float g_wp1[DMODEL_ * 1024];          // tf32-rounded w_p1
__device__ float g_wp2[1024 * 1024];             // tf32-rounded w_p2
__device__ int   g_mask[BN_ROWS];
__device__ int   g_na[B_];
__device__ int   g_base[B_];
__device__ int   g_total;
__device__ int   g_row2bn[BN_ROWS];

// ---------------- helpers ----------------
__device__ __forceinline__ void cp_async16(uint32_t smem_addr, const void* gptr) {
    asm volatile("cp.async.cg.shared.global [%0], [%1], 16;\n"
                 :: "r"(smem_addr), "l"(gptr));
}
__device__ __forceinline__ void cp_async_commit() {
    asm volatile("cp.async.commit_group;\n" ::);
}
__device__ __forceinline__ void cp_async_wait_all() {
    asm volatile("cp.async.wait_group 0;\n" ::: "memory");
}
__device__ __forceinline__ uint32_t f2tf32(float f) {
    uint32_t r;
    asm("cvt.rna.tf32.f32 %0, %1;" : "=r"(r) : "f"(f));
    return r;
}
__device__ __forceinline__ void mma_tf32(float* c, const uint32_t* a, const uint32_t* b) {
    asm volatile(
        "mma.sync.aligned.m16n8k8.row.col.f32.tf32.tf32.f32 "
        "{%0,%1,%2,%3}, {%4,%5,%6,%7}, {%8,%9}, {%0,%1,%2,%3};"
        : "+f"(c[0]), "+f"(c[1]), "+f"(c[2]), "+f"(c[3])
        : "r"(a[0]), "r"(a[1]), "r"(a[2]), "r"(a[3]), "r"(b[0]), "r"(b[1]));
}

// ---------------- active-agent mask + per-scene count ----------------
__global__ void mask_kernel(const float* __restrict__ x, int* __restrict__ mask,
                            int* __restrict__ na) {
    int b = blockIdx.x;
    int n = threadIdx.x;
    const float* p = x + (size_t)(b * NMAX_ + n) * (TOBS_ * DIN_);
    float s = 0.f;
#pragma unroll
    for (int j = 0; j < TOBS_ * DIN_; j++) s += p[j];
    __shared__ int cnt;
    if (n == 0) cnt = 0;
    __syncthreads();
    if (s > 0.0f) atomicAdd(&cnt, 1);
    __syncthreads();
    mask[b * NMAX_ + n] = (n < cnt) ? 1 : 0;
    if (n == 0) na[b] = cnt;
}

// ---------------- scan: base[b], total ----------------
__global__ void scan_kernel(const int* __restrict__ na, int* __restrict__ base,
                            int* __restrict__ total) {
    if (threadIdx.x == 0 && blockIdx.x == 0) {
        int acc = 0;
        for (int b = 0; b < B_; b++) {
            base[b] = acc;
            acc += na[b] + (na[b] < NMAX_ ? 1 : 0);
        }
        *total = acc;
    }
}

// ---------------- compact map ----------------
__global__ void cmap_init_kernel(int* __restrict__ row2bn) {
    int i = blockIdx.x * blockDim.x + threadIdx.x;
    if (i < BN_ROWS) row2bn[i] = 0;
}
__global__ void cmap_fill_kernel(const int* __restrict__ na, const int* __restrict__ base,
                                 int* __restrict__ row2bn) {
    int bn = blockIdx.x * blockDim.x + threadIdx.x;
    if (bn >= BN_ROWS) return;
    int b = bn >> 8, n = bn & 255;
    if (n <= na[b] && (n < NMAX_)) {
        if (n < na[b] || na[b] < NMAX_)
            row2bn[base[b] + n] = bn;
    }
}

// ---------------- embedding ----------------
__global__ void emb_kernel(const float* __restrict__ x, const float* __restrict__ w,
                           const float* __restrict__ bias, float* __restrict__ h) {
    size_t idx = (size_t)blockIdx.x * blockDim.x + threadIdx.x;
    if (idx >= (size_t)MROWS * E_) return;
    int e = (int)(idx & (E_ - 1));
    size_t row = idx >> 7;
    float x0 = x[row * 2 + 0];
    float x1 = x[row * 2 + 1];
    h[idx] = fmaf(x0, w[e], fmaf(x1, w[E_ + e], bias[e]));
}

// ---------------- conv weight transform (tf32-rounded) ----------------
__global__ void wprep_kernel(const float* __restrict__ w1, const float* __restrict__ w2,
                             float* __restrict__ out) {
    int t = blockIdx.x * blockDim.x + threadIdx.x;
    if (t >= 6 * 49152) return;
    int bc = t / 49152;
    int r = t % 49152;
    int kk = r >> 7;
    int o = r & 127;
    int tap = kk >> 7;
    int i = kk & 127;
    int blk = bc >> 1, conv = bc & 1;
    const float* src = conv ? w2 : w1;
    out[t] = __uint_as_float(f2tf32(src[(((size_t)(blk * 128 + o) * 128 + i) * 3) + tap]));
}

// ---------------- QKV weight/bias packing (weights tf32-rounded) ----------------
__global__ void qkvprep_kernel(const float* __restrict__ wq, const float* __restrict__ wk,
                               const float* __restrict__ wv,
                               const float* __restrict__ bq, const float* __restrict__ bk,
                               const float* __restrict__ bv,
                               float* __restrict__ wout, float* __restrict__ bout) {
    int t = blockIdx.x * blockDim.x + threadIdx.x;
    if (t < DMODEL_ * QKV_N) {
        int k = t / QKV_N;
        int n = t % QKV_N;
        int sel = n >> 9;
        int nn = n & 511;
        const float* src = (sel == 0) ? wq : (sel == 1) ? wk : wv;
        wout[t] = __uint_as_float(f2tf32(src[(size_t)k * DMODEL_ + nn]));
    }
    if (t < QKV_N) {
        int sel = t >> 9;
        int nn = t & 511;
        bout[t] = (sel == 0) ? bq[nn] : (sel == 1) ? bk[nn] : bv[nn];
    }
}

// ---------------- generic weight tf32 rounding copy ----------------
__global__ void wcvt_kernel(const float* __restrict__ src, float* __restrict__ dst, int count) {
    int i = blockIdx.x * blockDim.x + threadIdx.x;
    if (i < count) dst[i] = __uint_as_float(f2tf32(src[i]));
}

// ---------------- zero ONLY the per-scene representative inactive row ----------------
// Only row b*256+na[b] is read by the compact encoder gather among inactive rows;
// active rows are untouched, other inactive rows are never read. Exact.
__global__ void repzero_kernel(float* __restrict__ h, const int* __restrict__ na_) {
    int b = blockIdx.x;
    int na = na_[b];
    if (na >= NMAX_) return;
    float4 z = make_float4(0.f, 0.f, 0.f, 0.f);
    float4* p = (float4*)(h + (size_t)(b * NMAX_ + na) * HROW);
    p[threadIdx.x] = z;
    p[threadIdx.x + 256] = z;
}

// ================= tf32 tensor-core GEMM (mma.sync m16n8k8) =================
// BM=128, BN=128, BK=16; 8 warps: warp_m=wid&3 (32 rows), warp_n=wid>>2 (64 cols).
// A: register-staged -> smem (tf32-rounded at store). B: pre-rounded tf32 in
// global, cp.async -> smem, fragments are plain LDS. N must be %128==0.
// CONV=1: implicit-gemm gather (TCN) + all-inactive 8-agent block skip.
// GATHER=1: A rows via row2bn. d_total: compact M bound.
template <int CONV, int GATHER>
__global__ __launch_bounds__(256)
void tgemm_kernel(const float* __restrict__ A, const float* __restrict__ Bm,
                  const float* __restrict__ bias, const float* __restrict__ res,
                  float* __restrict__ C,
                  int N, int Kdim, int lda, int ldc,
                  int relu1, int hasres, int dil,
                  const int* __restrict__ mask,
                  const int* __restrict__ row2bn,
                  const int* __restrict__ d_total) {
    int tid = threadIdx.x;
    int m0 = blockIdx.x * 128;
    int n0 = blockIdx.y * 128;

    if (d_total && m0 >= *d_total) return;
    if (CONV) {
        int bn0 = m0 >> 4;
        int any = 0;
#pragma unroll
        for (int i = 0; i < 8; i++) any |= mask[bn0 + i];
        if (!any) return;
    }

    __shared__ float As[2][16][SMP];
    __shared__ float Bs[2][16][SMP];

    int lane = tid & 31;
    int wid = tid >> 5;
    int warp_m = wid & 3;
    int warp_n = wid >> 2;
    int lg = lane >> 2;
    int lt = lane & 3;

    int ar0 = (tid) >> 2,        ac0 = ((tid) & 3) * 4;
    int ar1 = (256 + tid) >> 2,  ac1 = ((256 + tid) & 3) * 4;
    int br0 = (tid) >> 5,        bc0 = ((tid) & 31) * 4;
    int br1 = (256 + tid) >> 5,  bc1 = ((256 + tid) & 31) * 4;

    size_t aoff0 = 0, aoff1 = 0;
    if (!CONV) {
        int r0m = m0 + ar0, r1m = m0 + ar1;
        if (GATHER) { r0m = row2bn[r0m]; r1m = row2bn[r1m]; }
        aoff0 = (size_t)r0m * lda + ac0;
        aoff1 = (size_t)r1m * lda + ac1;
    }

    uint32_t bs0 = (uint32_t)__cvta_generic_to_shared(&Bs[0][br0][bc0]);
    uint32_t bs1 = (uint32_t)__cvta_generic_to_shared(&Bs[0][br1][bc1]);
    const uint32_t BUFB = 16 * SMP * 4;

    float acc[2][8][4];
#pragma unroll
    for (int i = 0; i < 2; i++)
#pragma unroll
        for (int j = 0; j < 8; j++)
#pragma unroll
            for (int k = 0; k < 4; k++) acc[i][j][k] = 0.f;

    int ntiles = Kdim >> 4;

    auto fetchA = [&](int k0, int r, int c4, size_t aoff) -> float4 {
        if (CONV) {
            int m = m0 + r;
            int bn = m >> 4, t = m & 15;
            int kk = k0 + c4;
            int tap = kk >> 7;
            int e = kk & 127;
            int tsrc = t - (2 - tap) * dil;
            if (tsrc >= 0)
                return *(const float4*)(A + (size_t)bn * HROW + tsrc * E_ + e);
            return make_float4(0.f, 0.f, 0.f, 0.f);
        }
        return *(const float4*)(A + aoff + k0);
    };
    auto storeA = [&](int buf, float4 a0, float4 a1) {
        As[buf][ac0 + 0][ar0] = __uint_as_float(f2tf32(a0.x));
        As[buf][ac0 + 1][ar0] = __uint_as_float(f2tf32(a0.y));
        As[buf][ac0 + 2][ar0] = __uint_as_float(f2tf32(a0.z));
        As[buf][ac0 + 3][ar0] = __uint_as_float(f2tf32(a0.w));
        As[buf][ac1 + 0][ar1] = __uint_as_float(f2tf32(a1.x));
        As[buf][ac1 + 1][ar1] = __uint_as_float(f2tf32(a1.y));
        As[buf][ac1 + 2][ar1] = __uint_as_float(f2tf32(a1.z));
        As[buf][ac1 + 3][ar1] = __uint_as_float(f2tf32(a1.w));
    };
    auto cpB = [&](int buf, int k0) {
        cp_async16(bs0 + buf * BUFB, Bm + (size_t)(k0 + br0) * N + (n0 + bc0));
        cp_async16(bs1 + buf * BUFB, Bm + (size_t)(k0 + br1) * N + (n0 + bc1));
        cp_async_commit();
    };

    {
        float4 a0 = fetchA(0, ar0, ac0, aoff0);
        float4 a1 = fetchA(0, ar1, ac1, aoff1);
        storeA(0, a0, a1);
        cpB(0, 0);
        cp_async_wait_all();
    }
    __syncthreads();

    for (int it = 0; it < ntiles; it++) {
        int cur = it & 1;
        int nxt = cur ^ 1;

        float4 pa0, pa1;
        bool more = (it + 1) < ntiles;
        if (more) {
            int k0n = (it + 1) << 4;
            pa0 = fetchA(k0n, ar0, ac0, aoff0);
            pa1 = fetchA(k0n, ar1, ac1, aoff1);
            cpB(nxt, k0n);
        }

#pragma unroll
        for (int kc = 0; kc < 16; kc += 8) {
            uint32_t afr[2][4];
#pragma unroll
            for (int mt = 0; mt < 2; mt++) {
                int r0 = warp_m * 32 + mt * 16 + lg;
                afr[mt][0] = __float_as_uint(As[cur][kc + lt][r0]);
                afr[mt][1] = __float_as_uint(As[cur][kc + lt][r0 + 8]);
                afr[mt][2] = __float_as_uint(As[cur][kc + lt + 4][r0]);
                afr[mt][3] = __float_as_uint(As[cur][kc + lt + 4][r0 + 8]);
            }
            uint32_t bfr[8][2];
#pragma unroll
            for (int nt = 0; nt < 8; nt++) {
                int nn = warp_n * 64 + nt * 8 + lg;
                bfr[nt][0] = __float_as_uint(Bs[cur][kc + lt][nn]);
                bfr[nt][1] = __float_as_uint(Bs[cur][kc + lt + 4][nn]);
            }
#pragma unroll
            for (int mt = 0; mt < 2; mt++)
#pragma unroll
                for (int nt = 0; nt < 8; nt++)
                    mma_tf32(acc[mt][nt], afr[mt], bfr[nt]);
        }

        if (more) storeA(nxt, pa0, pa1);
        cp_async_wait_all();
        __syncthreads();
    }

#pragma unroll
    for (int mt = 0; mt < 2; mt++) {
        int rm = m0 + warp_m * 32 + mt * 16 + lg;
#pragma unroll
        for (int nt = 0; nt < 8; nt++) {
            int n = n0 + warp_n * 64 + nt * 8 + lt * 2;
#pragma unroll
            for (int half = 0; half < 2; half++) {
                int m = rm + half * 8;
                float v0 = acc[mt][nt][half * 2 + 0] + bias[n];
                float v1 = acc[mt][nt][half * 2 + 1] + bias[n + 1];
                if (relu1) { v0 = fmaxf(v0, 0.f); v1 = fmaxf(v1, 0.f); }
                if (hasres) {
                    v0 += res[(size_t)m * ldc + n];
                    v1 += res[(size_t)m * ldc + n + 1];
                    v0 = fmaxf(v0, 0.f);
                    v1 = fmaxf(v1, 0.f);
                }
                float2 v2 = make_float2(v0, v1);
                *(float2*)(C + (size_t)m * ldc + n) = v2;
            }
        }
    }
}

// ---------------- small SIMT GEMM (final N=24 projection, full fp32) ----------------
__global__ __launch_bounds__(256)
void gemm_small_kernel(const float* __restrict__ A, const float* __restrict__ Bm,
                       const float* __restrict__ bias, float* __restrict__ C,
                       int N, int Kdim, int lda, int ldc,
                       const int* __restrict__ d_total) {
    int tid = threadIdx.x;
    int m0 = blockIdx.x * 128;
    if (d_total && m0 >= *d_total) return;

    __shared__ float As[16][128];
    __shared__ float Bs[16][32];

    int tm = tid >> 4;
    int tn = tid & 15;
    float acc[8][2];
#pragma unroll
    for (int i = 0; i < 8; i++) { acc[i][0] = 0.f; acc[i][1] = 0.f; }

    for (int k0 = 0; k0 < Kdim; k0 += 16) {
#pragma unroll
        for (int rep = 0; rep < 2; rep++) {
            int f = rep * 256 + tid;
            int r = f >> 2;
            int c4 = (f & 3) * 4;
            float4 v = *(const float4*)(A + (size_t)(m0 + r) * lda + k0 + c4);
            As[c4 + 0][r] = v.x;
            As[c4 + 1][r] = v.y;
            As[c4 + 2][r] = v.z;
            As[c4 + 3][r] = v.w;
        }
        if (tid < 16 * 8) {
            int r = tid >> 3;
            int c = (tid & 7) * 4;
            float4 v;
            const float* bp = Bm + (size_t)(k0 + r) * N + c;
            v.x = (c + 0 < N) ? bp[0] : 0.f;
            v.y = (c + 1 < N) ? bp[1] : 0.f;
            v.z = (c + 2 < N) ? bp[2] : 0.f;
            v.w = (c + 3 < N) ? bp[3] : 0.f;
            *(float4*)&Bs[r][c] = v;
        }
        __syncthreads();
#pragma unroll
        for (int kk = 0; kk < 16; kk++) {
            float a[8];
            *(float4*)&a[0] = *(float4*)&As[kk][tm * 8];
            *(float4*)&a[4] = *(float4*)&As[kk][tm * 8 + 4];
            float b0 = Bs[kk][tn * 2], b1 = Bs[kk][tn * 2 + 1];
#pragma unroll
            for (int i = 0; i < 8; i++) {
                acc[i][0] = fmaf(a[i], b0, acc[i][0]);
                acc[i][1] = fmaf(a[i], b1, acc[i][1]);
            }
        }
        __syncthreads();
    }
#pragma unroll
    for (int i = 0; i < 8; i++) {
        int m = m0 + tm * 8 + i;
#pragma unroll
        for (int j = 0; j < 2; j++) {
            int n = tn * 2 + j;
            if (n < N)
                C[(size_t)m * ldc + n] = acc[i][j] + bias[n];
        }
    }
}

// ---------------- attention over compact rows, rep key multiplicity ----------------
__global__ __launch_bounds__(256)
void attn_kernel(const float* __restrict__ QKV, float* __restrict__ O,
                 const int* __restrict__ na_, const int* __restrict__ base_) {
    int bh = blockIdx.x;
    int b = bh >> 3, h = bh & 7;
    int tid = threadIdx.x;

    int na = na_[b];
    int base = base_[b];
    int rows = na + (na < NMAX_ ? 1 : 0);

    __shared__ float Ks[64][64];
    __shared__ float Vs[64][64];

    const float scale = 0.125f;
    int qrow = base + (tid < rows ? tid : rows - 1);
    float q[64];
    const float* qp = QKV + ((size_t)qrow * QKV_N) + h * 64;
#pragma unroll
    for (int i = 0; i < 16; i++) *(float4*)&q[i * 4] = *(const float4*)(qp + i * 4);

    float mrun = -1e30f, l = 0.f;
    float acc[64];
#pragma unroll
    for (int i = 0; i < 64; i++) acc[i] = 0.f;

    int ntile = (rows + 63) >> 6;
    for (int kt = 0; kt < ntile; kt++) {
        __syncthreads();
#pragma unroll
        for (int rep = 0; rep < 4; rep++) {
            int f = rep * 256 + tid;
            int r = f >> 4;
            int c = (f & 15) * 4;
            int kloc = kt * 64 + r;
            int krow = base + (kloc < rows ? kloc : rows - 1);
            size_t gi = ((size_t)krow * QKV_N) + h * 64 + c;
            *(float4*)&Ks[r][c] = *(const float4*)(QKV + gi + DMODEL_);
            *(float4*)&Vs[r][c] = *(const float4*)(QKV + gi + 2 * DMODEL_);
        }
        __syncthreads();
        int tmax = rows - kt * 64;
        if (tmax > 64) tmax = 64;
        for (int mm = 0; mm < tmax; mm++) {
            int kloc = kt * 64 + mm;
            float wf = (kloc == na) ? (float)(NMAX_ - na) : 1.f;
            float s = 0.f;
#pragma unroll
            for (int d = 0; d < 64; d++) s = fmaf(q[d], Ks[mm][d], s);
            s *= scale;
            if (s > mrun) {
                float corr = __expf(mrun - s);
                l = fmaf(l, corr, wf);
#pragma unroll
                for (int d = 0; d < 64; d++)
                    acc[d] = acc[d] * corr + wf * Vs[mm][d];
                mrun = s;
            } else {
                float p = __expf(s - mrun);
                float wp = wf * p;
                l += wp;
#pragma unroll
                for (int d = 0; d < 64; d++) acc[d] = fmaf(wp, Vs[mm][d], acc[d]);
            }
        }
    }
    if (tid < rows) {
        float inv = 1.f / l;
        float* op = O + ((size_t)(base + tid) * DMODEL_) + h * 64;
#pragma unroll
        for (int d = 0; d < 64; d++) op[d] = acc[d] * inv;
    }
}

// ---------------- scatter compact predictions to full output ----------------
__global__ void scatter_kernel(const float* __restrict__ p3c, float* __restrict__ out,
                               const int* __restrict__ na_, const int* __restrict__ base_) {
    int idx = blockIdx.x * blockDim.x + threadIdx.x;
    if (idx >= BN_ROWS * 24) return;
    int bn = idx / 24, j = idx - bn * 24;
    int b = bn >> 8, n = bn & 255;
    int nn = n < na_[b] ? n : na_[b];
    int c = base_[b] + nn;
    out[idx] = p3c[(size_t)c * 24 + j];
}

// ---------------- launch ----------------
extern "C" void kernel_launch(void* const* d_in, const int* in_sizes, int n_in,
                              void* d_out, int out_size) {
    const float* x      = (const float*)d_in[0];
    const float* w_emb  = (const float*)d_in[2];
    const float* b_emb  = (const float*)d_in[3];
    const float* tcn_w1 = (const float*)d_in[4];
    const float* tcn_b1 = (const float*)d_in[5];
    const float* tcn_w2 = (const float*)d_in[6];
    const float* tcn_b2 = (const float*)d_in[7];
    const float* w_enc  = (const float*)d_in[8];
    const float* b_enc  = (const float*)d_in[9];
    const float* wq     = (const float*)d_in[10];
    const float* bq     = (const float*)d_in[11];
    const float* wk     = (const float*)d_in[12];
    const float* bk     = (const float*)d_in[13];
    const float* wv     = (const float*)d_in[14];
    const float* bv     = (const float*)d_in[15];
    const float* wo     = (const float*)d_in[16];
    const float* bo     = (const float*)d_in[17];
    const float* w_p1   = (const float*)d_in[18];
    const float* b_p1   = (const float*)d_in[19];
    const float* w_p2   = (const float*)d_in[20];
    const float* b_p2   = (const float*)d_in[21];
    const float* w_p3   = (const float*)d_in[22];
    const float* b_p3   = (const float*)d_in[23];
    float* out = (float*)d_out;

    float *h, *z, *feat, *qkv, *att, *o, *p1, *p2, *p3c, *wc, *wqkv, *bqkv;
    float *wenc, *wo_c, *wp1, *wp2;
    int *mask, *na, *base, *total, *row2bn;
    cudaGetSymbolAddress((void**)&h,      g_h);
    cudaGetSymbolAddress((void**)&z,      g_z);
    cudaGetSymbolAddress((void**)&feat,   g_feat);
    cudaGetSymbolAddress((void**)&qkv,    g_qkv);
    cudaGetSymbolAddress((void**)&att,    g_att);
    cudaGetSymbolAddress((void**)&o,      g_o);
    cudaGetSymbolAddress((void**)&p1,     g_p1);
    cudaGetSymbolAddress((void**)&p2,     g_p2);
    cudaGetSymbolAddress((void**)&p3c,    g_p3c);
    cudaGetSymbolAddress((void**)&wc,     g_wc);
    cudaGetSymbolAddress((void**)&wqkv,   g_wqkv);
    cudaGetSymbolAddress((void**)&bqkv,   g_bqkv);
    cudaGetSymbolAddress((void**)&wenc,   g_wenc);
    cudaGetSymbolAddress((void**)&wo_c,   g_wo);
    cudaGetSymbolAddress((void**)&wp1,    g_wp1);
    cudaGetSymbolAddress((void**)&wp2,    g_wp2);
    cudaGetSymbolAddress((void**)&mask,   g_mask);
    cudaGetSymbolAddress((void**)&na,     g_na);
    cudaGetSymbolAddress((void**)&base,   g_base);
    cudaGetSymbolAddress((void**)&total,  g_total);
    cudaGetSymbolAddress((void**)&row2bn, g_row2bn);

    // 1) mask + compaction metadata + embedding + weight prep (tf32 pre-rounding)
    mask_kernel<<<B_, NMAX_>>>(x, mask, na);
    scan_kernel<<<1, 32>>>(na, base, total);
    cmap_init_kernel<<<BN_ROWS / 256, 256>>>(row2bn);
    cmap_fill_kernel<<<BN_ROWS / 256, 256>>>(na, base, row2bn);
    emb_kernel<<<(int)(((size_t)MROWS * E_ + 255) / 256), 256>>>(x, w_emb, b_emb, h);
    wprep_kernel<<<(6 * 49152 + 255) / 256, 256>>>(tcn_w1, tcn_w2, wc);
    qkvprep_kernel<<<(DMODEL_ * QKV_N + 255) / 256, 256>>>(wq, wk, wv, bq, bk, bv, wqkv, bqkv);
    wcvt_kernel<<<(HROW * DMODEL_ + 255) / 256, 256>>>(w_enc, wenc, HROW * DMODEL_);
    wcvt_kernel<<<(DMODEL_ * DMODEL_ + 255) / 256, 256>>>(wo, wo_c, DMODEL_ * DMODEL_);
    wcvt_kernel<<<(DMODEL_ * 1024 + 255) / 256, 256>>>(w_p1, wp1, DMODEL_ * 1024);
    wcvt_kernel<<<(1024 * 1024 + 255) / 256, 256>>>(w_p2, wp2, 1024 * 1024);

    // 2) TCN: 3 residual blocks (dil = 1,2,4); tf32 tensor path, inactive blocks skipped
    for (int blk = 0; blk < 3; blk++) {
        int dil = 1 << blk;
        tgemm_kernel<1, 0><<<dim3(MROWS / 128, 1), 256>>>(
            h, wc + (size_t)(blk * 2 + 0) * 49152, tcn_b1 + blk * 128, nullptr, z,
            128, 384, 0, 128, 1, 0, dil, mask, nullptr, nullptr);
        tgemm_kernel<1, 0><<<dim3(MROWS / 128, 1), 256>>>(
            z, wc + (size_t)(blk * 2 + 1) * 49152, tcn_b2 + blk * 128, h, h,
            128, 384, 0, 128, 1, 1, dil, mask, nullptr, nullptr);
    }

    // 3) zero rep rows only, then COMPACT encoder GEMM (gather via row2bn)
    repzero_kernel<<<B_, 256>>>(h, na);
    tgemm_kernel<0, 1><<<dim3(BN_ROWS / 128, DMODEL_ / 128), 256>>>(
        h, wenc, b_enc, nullptr, feat, DMODEL_, HROW, HROW, DMODEL_, 0, 0, 0,
        nullptr, row2bn, total);

    // 4) compact QKV + attention + output projection
    tgemm_kernel<0, 0><<<dim3(BN_ROWS / 128, QKV_N / 128), 256>>>(
        feat, wqkv, bqkv, nullptr, qkv, QKV_N, DMODEL_, DMODEL_, QKV_N, 0, 0, 0,
        nullptr, nullptr, total);
    attn_kernel<<<B_ * 8, 256>>>(qkv, att, na, base);
    tgemm_kernel<0, 0><<<dim3(BN_ROWS / 128, DMODEL_ / 128), 256>>>(
        att, wo_c, bo, nullptr, o, DMODEL_, DMODEL_, DMODEL_, DMODEL_, 0, 0, 0,
        nullptr, nullptr, total);

    // 5) compact predictor MLP, then scatter to full output
    tgemm_kernel<0, 0><<<dim3(BN_ROWS / 128, 1024 / 128), 256>>>(
        o, wp1, b_p1, nullptr, p1, 1024, DMODEL_, DMODEL_, 1024, 1, 0, 0,
        nullptr, nullptr, total);
    tgemm_kernel<0, 0><<<dim3(BN_ROWS / 128, 1024 / 128), 256>>>(
        p1, wp2, b_p2, nullptr, p2, 1024, 1024, 1024, 1024, 1, 0, 0,
        nullptr, nullptr, total);
    gemm_small_kernel<<<BN_ROWS / 128, 256>>>(
        p2, w_p3, b_p3, p3c, 24, 1024, 1024, 24, total);
    scatter_kernel<<<(BN_ROWS * 24 + 255) / 256, 256>>>(p3c, out, na, base);
}